// round 11
// baseline (speedup 1.0000x reference)
#include <cuda_runtime.h>
#include <cuda_fp16.h>
#include <math.h>

#define BB 8
#define CC 256
#define HH 128
#define WW 128
#define HWs 16384
#define NBCHW (BB*CC*HWs)
#define MS 134
typedef unsigned long long ull;
typedef unsigned int u32;

__device__ float g_buf[2*NBCHW];
__device__ float g_gate[BB*CC];
__device__ float g_amean[BB*CC];
__device__ float g_amax[BB*CC];
__device__ float g_mA[BB*HWs];
__device__ float g_vfinal[BB*HWs];
__device__ float g_bcat[1280];
__device__ __align__(16) __half g_imgh[335544320];
__device__ __align__(16) __half g_imgl[335544320];
__device__ __align__(16) __half g_Mh[16777216];
__device__ __align__(16) __half g_wih[2097152];
__device__ __align__(16) __half g_wil[262144];
#define IK(k) ((long)(k)*33554432L)

__device__ __forceinline__ float sigmoidf_(float x){ return 1.0f/(1.0f+expf(-x)); }
__device__ __forceinline__ u32 smem_u32(const void* p){
    u32 a; asm("{ .reg .u64 t; cvta.to.shared.u64 t, %1; cvt.u32.u64 %0, t; }" : "=r"(a) : "l"(p)); return a; }
__device__ __forceinline__ u32 pack2(float a, float b){
    __half2 t = __floats2half2_rn(a, b); return *(u32*)&t; }
__device__ __forceinline__ void w2(__half* oh, __half* ol, long idx, float a, float b){
    u32 h = pack2(a,b); __half2 hv = *(__half2*)&h;
    ((u32*)oh)[idx>>1] = h;
    if (ol) ((u32*)ol)[idx>>1] = pack2(a-__half2float(hv.x), b-__half2float(hv.y));
}
__device__ __forceinline__ void ldsm4(u32& r0,u32& r1,u32& r2,u32& r3,u32 a){
    asm volatile("ldmatrix.sync.aligned.m8n8.x4.shared.b16 {%0,%1,%2,%3}, [%4];"
        :"=r"(r0),"=r"(r1),"=r"(r2),"=r"(r3):"r"(a)); }
__device__ __forceinline__ void ldsm4t(u32& r0,u32& r1,u32& r2,u32& r3,u32 a){
    asm volatile("ldmatrix.sync.aligned.m8n8.x4.trans.shared.b16 {%0,%1,%2,%3}, [%4];"
        :"=r"(r0),"=r"(r1),"=r"(r2),"=r"(r3):"r"(a)); }
__device__ __forceinline__ void mmah(float* c, const u32* a, const u32* b){
    asm volatile("mma.sync.aligned.m16n8k16.row.col.f32.f16.f16.f32 "
        "{%0,%1,%2,%3},{%4,%5,%6,%7},{%8,%9},{%0,%1,%2,%3};"
        :"+f"(c[0]),"+f"(c[1]),"+f"(c[2]),"+f"(c[3])
        :"r"(a[0]),"r"(a[1]),"r"(a[2]),"r"(a[3]),"r"(b[0]),"r"(b[1])); }
__device__ __forceinline__ void cpa(u32 d, const void* s){
    asm volatile("cp.async.cg.shared.global [%0], [%1], 16;"::"r"(d),"l"(s)); }
__device__ __forceinline__ void cpcommit(){ asm volatile("cp.async.commit_group;":::"memory"); }
__device__ __forceinline__ void cpwait1(){ asm volatile("cp.async.wait_group 1;":::"memory"); }
__device__ __forceinline__ void cpwait0(){ asm volatile("cp.async.wait_group 0;":::"memory"); }

// ---- pool: fp32 + fp16-hi images ----
__global__ void pool_k(const float* __restrict__ xp, float* __restrict__ y1, float* __restrict__ y2,
                       __half* __restrict__ y1h, __half* __restrict__ y2h){
    long idx = (long)blockIdx.x*256 + threadIdx.x;
    if (idx >= (long)NBCHW) return;
    int w = (int)(idx & 127), h = (int)((idx>>7)&127);
    long base = idx - (long)(h*WW+w);
    float s=0.f, mx=-INFINITY;
    #pragma unroll
    for (int dy=-1;dy<=1;dy++){ int hh=h+dy; if(hh<0||hh>=HH) continue;
        #pragma unroll
        for (int dx=-1;dx<=1;dx++){ int ww=w+dx; if(ww<0||ww>=WW) continue;
            float v = xp[base+hh*WW+ww]; s+=v; mx=fmaxf(mx,v); } }
    float a = s*(1.f/9.f);
    y1[idx]=a; y2[idx]=mx;
    y1h[idx]=__float2half_rn(a); y2h[idx]=__float2half_rn(mx);
}
__global__ void reduce_k(const float* __restrict__ x, float* __restrict__ mean, float* __restrict__ mxo){
    __shared__ float ss[256], sm[256];
    int bc=blockIdx.x, t=threadIdx.x;
    const float* p = x + (long)bc*HWs;
    float s=0.f, m=-INFINITY;
    for (int i=t;i<HWs;i+=256){ float v=p[i]; s+=v; m=fmaxf(m,v); }
    ss[t]=s; sm[t]=m; __syncthreads();
    for (int o=128;o>0;o>>=1){ if (t<o){ ss[t]+=ss[t+o]; sm[t]=fmaxf(sm[t],sm[t+o]); } __syncthreads(); }
    if (t==0){ mean[bc]=ss[0]*(1.f/(float)HWs); mxo[bc]=sm[0]; }
}
__global__ void cagate_k(const float* __restrict__ amean, const float* __restrict__ amax,
    const float* __restrict__ aw1, const float* __restrict__ ab1,
    const float* __restrict__ aw2, const float* __restrict__ ab2,
    const float* __restrict__ mw1, const float* __restrict__ mb1,
    const float* __restrict__ mw2, const float* __restrict__ mb2, float* __restrict__ gate){
    __shared__ float ha[16], hm[16];
    int b=blockIdx.x, t=threadIdx.x;
    if (t<16){ float s=ab1[t]; for (int i=0;i<CC;i++) s+=aw1[t*CC+i]*amean[b*CC+i]; ha[t]=fmaxf(s,0.f); }
    else if (t<32){ int u=t-16; float s=mb1[u]; for (int i=0;i<CC;i++) s+=mw1[u*CC+i]*amax[b*CC+i]; hm[u]=fmaxf(s,0.f); }
    __syncthreads();
    float g = ab2[t]+mb2[t];
    #pragma unroll
    for (int k=0;k<16;k++) g += aw2[t*16+k]*ha[k] + mw2[t*16+k]*hm[k];
    gate[b*CC+t] = sigmoidf_(g);
}
__global__ void cvt_k(const float* __restrict__ src, __half* __restrict__ oh){
    long i4 = ((long)blockIdx.x*256 + threadIdx.x)*4;
    float4 v = *(const float4*)(src + i4);
    ((u32*)oh)[i4>>1]     = pack2(v.x, v.y);
    ((u32*)oh)[(i4>>1)+1] = pack2(v.z, v.w);
}
__global__ void cvtw_k(const float* __restrict__ W, int RS, int K, const float* __restrict__ gate,
                       __half* __restrict__ oh, __half* __restrict__ ol){
    int idx = blockIdx.x*256 + threadIdx.x;
    int b = idx/(256*K); int rem = idx - b*256*K; int m = rem/K, k = rem - m*K;
    float v = W[(long)m*RS + k];
    if (gate) v *= gate[b*256 + k];
    __half h = __float2half_rn(v);
    oh[idx] = h;
    if (ol) ol[idx] = __float2half_rn(v - __half2float(h));
}
__global__ void bcat_k(const float* __restrict__ b1, const float* __restrict__ b2,
                       const float* __restrict__ b3, float* __restrict__ o){
    int t = blockIdx.x*256 + threadIdx.x;
    if (t<256) o[t]=b1[t];
    else if (t<512) o[t]=b2[t-256];
    else if (t<768) o[t]=b2[t-512];
    else if (t<1024) o[t]=b1[t-768];
    else if (t<1280) o[t]=b3[t-1024];
}

// ---- HMMA GEMM with batch+group dims: by = g*8 + b ----
#define STG 49664u
#define GSM (2*49664)
__global__ void __launch_bounds__(256,1) gemm_mma(
    const __half* __restrict__ Wh, const __half* __restrict__ Wl, long wBS, long wGS, int K,
    const __half* __restrict__ X0h, const __half* __restrict__ X1h, long xGS,
    float* __restrict__ Yf, __half* __restrict__ Yh, __half* __restrict__ Yl, long yGS,
    const float* __restrict__ bias, int biasGS, int epi,
    const float* __restrict__ E0, long e0GS, const float* __restrict__ E1)
{
    extern __shared__ __align__(16) char smem[];
    u32 sm = smem_u32(smem);
    int tid=threadIdx.x, lane=tid&31, wid=tid>>5;
    int n0 = blockIdx.x*128;
    int by = blockIdx.y, b = by & 7, g = by >> 3;
    int wm = (wid&1)*128, wn = (wid>>1)*32;
    int lr = lane&15, lc8 = (lane>>4)*8;
    const __half* WhB = Wh + (long)b*wBS + (long)g*wGS;
    const __half* WlB = Wl ? (Wl + (long)b*wBS + (long)g*wGS) : 0;
    const __half* X0 = X0h + (long)g*xGS;
    const float* biasg = bias + g*biasGS;
    int NC = K>>5;
    float acc[32][4];
    #pragma unroll
    for (int i=0;i<32;i++){ acc[i][0]=0;acc[i][1]=0;acc[i][2]=0;acc[i][3]=0; }
    for (int c=0; c<=NC; c++){
        if (c<NC){
            u32 st = sm + (u32)(c&1)*STG;
            int kb = c*32;
            #pragma unroll
            for (int j=0;j<4;j++){
                int o=tid+256*j, r=o>>2, cb=o&3;
                u32 d = st + (u32)(r*80+cb*16);
                cpa(d, WhB + (size_t)r*K + kb + cb*8);
                if (WlB) cpa(d + 20480u, WlB + (size_t)r*K + kb + cb*8);
            }
            const __half *xh=X0; int kk=kb;
            if (kk>=256){ xh=X1h; kk-=256; }
            #pragma unroll
            for (int j=0;j<2;j++){
                int o=tid+256*j, r=o>>4, cb=o&15;
                size_t s = ((size_t)b*256 + kk + r)*HWs + n0 + cb*8;
                cpa(st + 40960u + (u32)(r*272+cb*16), xh + s);
            }
            cpcommit();
        }
        if (c==0) continue;
        if (c<NC) cpwait1(); else cpwait0();
        __syncthreads();
        u32 sA = sm + (u32)((c-1)&1)*STG;
        #pragma unroll
        for (int ks=0; ks<32; ks+=16){
            u32 bh[4][2];
            #pragma unroll
            for (int pr=0; pr<2; pr++){
                u32 off = (u32)((ks+lr)*272 + (wn+pr*16+lc8)*2);
                ldsm4t(bh[pr*2][0],bh[pr*2][1],bh[pr*2+1][0],bh[pr*2+1][1], sA+40960u+off);
            }
            #pragma unroll
            for (int mt=0; mt<8; mt++){
                u32 ah[4], al[4];
                u32 off = (u32)((wm+mt*16+lr)*80 + (ks+lc8)*2);
                ldsm4(ah[0],ah[1],ah[2],ah[3], sA+off);
                if (WlB) ldsm4(al[0],al[1],al[2],al[3], sA+20480u+off);
                #pragma unroll
                for (int nt=0; nt<4; nt++){
                    float* cc = acc[mt*4+nt];
                    mmah(cc, ah, bh[nt]);
                    if (WlB) mmah(cc, al, bh[nt]);
                }
            }
        }
        __syncthreads();
    }
    __half* Yhg = Yh ? Yh + (long)g*yGS : 0;
    __half* Ylg = Yl ? Yl + (long)g*yGS : 0;
    #pragma unroll
    for (int mt=0; mt<8; mt++){
        #pragma unroll
        for (int nt=0; nt<4; nt++){
            float* cc = acc[mt*4+nt];
            int n = n0 + wn + nt*8 + (lane&3)*2;
            #pragma unroll
            for (int hlf=0; hlf<2; hlf++){
                int m = wm + mt*16 + (lane>>2) + hlf*8;
                float v0 = cc[hlf*2] + biasg[m], v1 = cc[hlf*2+1] + biasg[m];
                long yb = ((long)b*CC + m)*HWs + n;
                if (epi==1){ v0=fmaxf(v0,0.f); v1=fmaxf(v1,0.f); }
                else if (epi==2){ long e=(long)g*e0GS+yb; v0+=E0[e]; v1+=E0[e+1]; }
                else if (epi==3){ v0=sigmoidf_(v0)*E0[yb]; v1=sigmoidf_(v1)*E0[yb+1]; }
                else if (epi==4){ float wl=E1[(long)m*513+512]; long eb=(long)b*HWs+n;
                    v0+=wl*E0[eb]; v1+=wl*E0[eb+1]; }
                if (Yf){ float2 st={v0,v1}; *(float2*)(Yf+yb)=st; }
                else   w2(Yhg, Ylg, yb, v0, v1);
            }
        }
    }
}

// ---- HMMA score (A=Q 2-pass, B=S hi); softmax over j ----
template<int WRITE_M>
__global__ void __launch_bounds__(256,1) score_mma(
    const __half* __restrict__ Qh, const __half* __restrict__ Ql,
    const __half* __restrict__ Sh,
    __half* __restrict__ Mh, float* __restrict__ mOut)
{
    extern __shared__ __align__(16) char smem[];
    u32 sm = smem_u32(smem);
    float* smE = (float*)smem;
    int tid=threadIdx.x, lane=tid&31, wid=tid>>5;
    int h = blockIdx.x, b = blockIdx.y;
    int wm=(wid&1)*64, wn=(wid>>1)*32;
    int lr=lane&15, lc8=(lane>>4)*8;
    float acc[16][4];
    #pragma unroll
    for (int i=0;i<16;i++){ acc[i][0]=0;acc[i][1]=0;acc[i][2]=0;acc[i][3]=0; }
    for (int c=0;c<=8;c++){
        if (c<8){
            u32 st = sm + (u32)(c&1)*26112u;
            int kb = c*32;
            #pragma unroll
            for (int j=0;j<2;j++){
                int o = tid + 256*j, r = o>>4, cb = o&15;
                size_t s = ((size_t)(b*256 + kb + r))*HWs + h*128 + cb*8;
                u32 d = st + (u32)(r*272 + cb*16);
                cpa(d, Qh+s); cpa(d+8704u, Ql+s); cpa(d+17408u, Sh+s);
            }
            cpcommit();
        }
        if (c==0) continue;
        if (c<8) cpwait1(); else cpwait0();
        __syncthreads();
        u32 sA = sm + (u32)((c-1)&1)*26112u;
        #pragma unroll
        for (int ks=0;ks<32;ks+=16){
            u32 bh[4][2];
            #pragma unroll
            for (int pr=0;pr<2;pr++){
                u32 off = (u32)((ks+lr)*272 + (wn+pr*16+lc8)*2);
                ldsm4t(bh[pr*2][0],bh[pr*2][1],bh[pr*2+1][0],bh[pr*2+1][1], sA+17408u+off);
            }
            #pragma unroll
            for (int mt=0;mt<4;mt++){
                u32 r0,r1,r2,r3,q0,q1,q2,q3;
                u32 off = (u32)((ks+lr)*272 + (wm+mt*16+lc8)*2);
                ldsm4t(r0,r1,r2,r3, sA+off);
                ldsm4t(q0,q1,q2,q3, sA+8704u+off);
                u32 ah[4]={r0,r2,r1,r3}, al[4]={q0,q2,q1,q3};
                #pragma unroll
                for (int nt=0;nt<4;nt++){
                    float* cc = acc[mt*4+nt];
                    mmah(cc, ah, bh[nt]); mmah(cc, al, bh[nt]);
                }
            }
        }
        __syncthreads();
    }
    #pragma unroll
    for (int mt=0;mt<4;mt++)
        #pragma unroll
        for (int nt=0;nt<4;nt++){
            float* cc = acc[mt*4+nt];
            int n = wn + nt*8 + (lane&3)*2;
            #pragma unroll
            for (int hlf=0;hlf<2;hlf++){
                int m = wm + mt*16 + (lane>>2) + hlf*8;
                smE[m*132+n] = cc[hlf*2]; smE[m*132+n+1] = cc[hlf*2+1];
            }
        }
    __syncthreads();
    int row = tid>>1, c0 = (tid&1)*64;
    float* rp = smE + row*132 + c0;
    float mx = -INFINITY;
    for (int j=0;j<64;j++) mx = fmaxf(mx, rp[j]);
    mx = fmaxf(mx, __shfl_xor_sync(0xffffffffu, mx, 1));
    float sum = 0.f;
    for (int j=0;j<64;j++){ float e = expf(rp[j]-mx); rp[j] = e; sum += e; }
    sum += __shfl_xor_sync(0xffffffffu, sum, 1);
    float inv = 1.f/sum;
    if (WRITE_M){
        long base = ((long)(b*128+h)*128 + row)*128 + c0;
        for (int j=0;j<64;j+=2)
            ((u32*)Mh)[(base+j)>>1] = pack2(rp[j]*inv, rp[j+1]*inv);
    } else {
        for (int j=0;j<64;j++) rp[j] *= inv;
        __syncthreads();
        if (tid < 128){
            float t = 0.f;
            for (int i=0;i<128;i++) t += smE[i*132+tid];
            mOut[(long)b*HWs + h*128 + tid] = (t>0.1f)?0.f:1.f;
        }
    }
}

// ---- HMMA attend ----
__global__ void __launch_bounds__(256,1) attend_mma(
    const __half* __restrict__ Mh,
    const __half* __restrict__ Vh, const __half* __restrict__ Vl,
    __half* __restrict__ Oh)
{
    extern __shared__ __align__(16) char smem[];
    u32 sm = smem_u32(smem);
    int tid=threadIdx.x, lane=tid&31, wid=tid>>5;
    int c0 = blockIdx.x*128, bh = blockIdx.y, b = bh>>7, h = bh&127;
    int wm=(wid&1)*64, wn=(wid>>1)*32;
    int lr=lane&15, lc8=(lane>>4)*8;
    int tile=lane>>3, lrow=lane&7;
    float acc[16][4];
    #pragma unroll
    for (int i=0;i<16;i++){ acc[i][0]=0;acc[i][1]=0;acc[i][2]=0;acc[i][3]=0; }
    for (int c=0;c<=4;c++){
        if (c<4){
            u32 st = sm + (u32)(c&1)*30720u;
            int kb = c*32;
            #pragma unroll
            for (int j=0;j<2;j++){
                int o = tid + 256*j, r = o>>2, cb = o&3;
                u32 d = st + (u32)(r*80 + cb*16);
                size_t s = ((size_t)(b*256 + c0 + r))*HWs + h*128 + kb + cb*8;
                cpa(d, Vh+s); cpa(d+10240u, Vl+s);
                size_t s2 = (((size_t)(b*128+h)*128 + r))*128 + kb + cb*8;
                cpa(d+20480u, Mh+s2);
            }
            cpcommit();
        }
        if (c==0) continue;
        if (c<4) cpwait1(); else cpwait0();
        __syncthreads();
        u32 sA = sm + (u32)((c-1)&1)*30720u;
        #pragma unroll
        for (int ks=0;ks<32;ks+=16){
            u32 bh_[4][2];
            #pragma unroll
            for (int pr=0;pr<2;pr++){
                u32 off = (u32)(((wn+pr*16+(tile>>1)*8+lrow)*40 + ks + (tile&1)*8)*2);
                u32 r0,r1,r2,r3;
                ldsm4(r0,r1,r2,r3, sA+20480u+off);
                bh_[pr*2][0]=r0; bh_[pr*2][1]=r1; bh_[pr*2+1][0]=r2; bh_[pr*2+1][1]=r3;
            }
            #pragma unroll
            for (int mt=0;mt<4;mt++){
                u32 ah[4], al[4];
                u32 off = (u32)((wm+mt*16+lr)*80 + (ks+lc8)*2);
                ldsm4(ah[0],ah[1],ah[2],ah[3], sA+off);
                ldsm4(al[0],al[1],al[2],al[3], sA+10240u+off);
                #pragma unroll
                for (int nt=0;nt<4;nt++){
                    float* cc = acc[mt*4+nt];
                    mmah(cc, ah, bh_[nt]); mmah(cc, al, bh_[nt]);
                }
            }
        }
        __syncthreads();
    }
    #pragma unroll
    for (int mt=0;mt<4;mt++)
        #pragma unroll
        for (int nt=0;nt<4;nt++){
            float* cc = acc[mt*4+nt];
            int n = wn + nt*8 + (lane&3)*2;
            #pragma unroll
            for (int hlf=0;hlf<2;hlf++){
                int m = wm + mt*16 + (lane>>2) + hlf*8;
                long idx = ((long)(b*256 + c0 + m))*HWs + h*128 + n;
                ((u32*)Oh)[idx>>1] = pack2(cc[hlf*2], cc[hlf*2+1]);
            }
        }
}

// ---- fused morphology: whole chain per batch in smem ----
__device__ void morp(float* dst, const float* src, int r, int erode, int D, int t, int NT){
    int r2 = r*r;
    for (int i=t; i<D*D; i+=NT){
        int h = i/D, w = i - h*D;
        float res = erode ? 1.f : 0.f;
        for (int dy=-r; dy<=r; dy++) for (int dx=-r; dx<=r; dx++){
            if (dy*dy+dx*dx > r2) continue;
            int hh=h+dy, ww=w+dx;
            float v = (hh>=0&&hh<D&&ww>=0&&ww<D) ? src[hh*MS+ww] : 0.f;
            if (erode){ if (v<0.5f) res=0.f; } else if (v>0.5f) res=1.f;
        }
        dst[h*MS+w] = res;
    }
}
__global__ void morphall_k(const float* __restrict__ src, float* __restrict__ dst){
    extern __shared__ float sA[];
    float* A = sA; float* B = sA + MS*MS;
    int b = blockIdx.x, t = threadIdx.x, NT = blockDim.x;
    for (int i=t;i<MS*MS;i+=NT){ A[i]=0.f; B[i]=0.f; }
    __syncthreads();
    for (int i=t;i<HWs;i+=NT){ int h=i>>7, w=i&127; A[h*MS+w]=src[(long)b*HWs+i]; }
    __syncthreads();
    morp(B,A,2,1,128,t,NT); __syncthreads();
    morp(A,B,2,0,128,t,NT); __syncthreads();
    morp(B,A,1,0,128,t,NT); __syncthreads();
    morp(A,B,1,1,128,t,NT); __syncthreads();
    // pad3 into B over 134 domain
    for (int i=t;i<MS*MS;i+=NT){
        int h=i/MS, w=i-h*MS;
        float v = 0.f;
        if (h>=3 && h<131 && w>=3 && w<131) v = A[(h-3)*MS + (w-3)];
        B[i] = v;
    }
    __syncthreads();
    morp(A,B,3,0,MS,t,NT); __syncthreads();
    morp(B,A,3,1,MS,t,NT); __syncthreads();
    for (int i=t;i<HWs;i+=NT){ int h=i>>7, w=i&127; dst[(long)b*HWs+i] = 1.f - B[(h+3)*MS + (w+3)]; }
}

extern "C" void kernel_launch(void* const* d_in, const int* in_sizes, int n_in,
                              void* d_out, int out_size) {
    const float* x_p=(const float*)d_in[0];  const float* x_c=(const float*)d_in[1];
    const float* pa_w1=(const float*)d_in[2];const float* pa_b1=(const float*)d_in[3];
    const float* pa_w2=(const float*)d_in[4];const float* pa_b2=(const float*)d_in[5];
    const float* pa_wc=(const float*)d_in[6];const float* pa_bc=(const float*)d_in[7];
    const float* ca_aw1=(const float*)d_in[8];const float* ca_ab1=(const float*)d_in[9];
    const float* ca_aw2=(const float*)d_in[10];const float* ca_ab2=(const float*)d_in[11];
    const float* ca_mw1=(const float*)d_in[12];const float* ca_mb1=(const float*)d_in[13];
    const float* ca_mw2=(const float*)d_in[14];const float* ca_mb2=(const float*)d_in[15];
    const float* b1_w=(const float*)d_in[16];const float* b1_b=(const float*)d_in[17];
    const float* b2_w=(const float*)d_in[18];const float* b2_b=(const float*)d_in[19];
    const float* b3_w=(const float*)d_in[20];const float* b3_b=(const float*)d_in[21];
    const float* fus_w=(const float*)d_in[22];const float* fus_b=(const float*)d_in[23];
    float* out=(float*)d_out;

    float *buf,*gate,*amean,*amax,*mA,*vfin,*bcat;
    __half *ih,*il,*wh,*wl,*Mh;
    cudaGetSymbolAddress((void**)&buf,g_buf);
    cudaGetSymbolAddress((void**)&gate,g_gate);
    cudaGetSymbolAddress((void**)&amean,g_amean); cudaGetSymbolAddress((void**)&amax,g_amax);
    cudaGetSymbolAddress((void**)&mA,g_mA);
    cudaGetSymbolAddress((void**)&vfin,g_vfinal);
    cudaGetSymbolAddress((void**)&bcat,g_bcat);
    cudaGetSymbolAddress((void**)&ih,g_imgh); cudaGetSymbolAddress((void**)&il,g_imgl);
    cudaGetSymbolAddress((void**)&wh,g_wih);  cudaGetSymbolAddress((void**)&wl,g_wil);
    cudaGetSymbolAddress((void**)&Mh,g_Mh);
    cudaFuncSetAttribute(gemm_mma, cudaFuncAttributeMaxDynamicSharedMemorySize, GSM);
    cudaFuncSetAttribute(score_mma<1>, cudaFuncAttributeMaxDynamicSharedMemorySize, 67584);
    cudaFuncSetAttribute(score_mma<0>, cudaFuncAttributeMaxDynamicSharedMemorySize, 67584);
    cudaFuncSetAttribute(attend_mma, cudaFuncAttributeMaxDynamicSharedMemorySize, 61440);
    cudaFuncSetAttribute(morphall_k, cudaFuncAttributeMaxDynamicSharedMemorySize, 2*MS*MS*4);

    // weight image element offsets
    const long W1=0, W2=65536, WC=131072, B1=262144, B2=327680, FU=393216;
    const long B2G=524288, B1G=1048576, B3R=1572864;

    // 1: pool (y1h->I3, y2h->I4)
    pool_k<<<NBCHW/256,256>>>(x_p, buf, buf+NBCHW, ih+IK(3), ih+IK(4));
    // 2-3
    reduce_k<<<BB*CC,256>>>(x_c, amean, amax);
    cagate_k<<<BB,256>>>(amean,amax,ca_aw1,ca_ab1,ca_aw2,ca_ab2,ca_mw1,ca_mb1,ca_mw2,ca_mb2,gate);
    // 4-5: W1 (1-pass), W2 (2-pass)
    cvtw_k<<<256,256>>>(pa_w1,256,256,0, wh+W1, 0);
    cvtw_k<<<256,256>>>(pa_w2,256,256,0, wh+W2, wl+W2);
    // 6: merged h1+h2 (relu) -> I5,I6   [ncu capture target]
    dim3 g2(128,16), g1(128,8), g3(128,24);
    gemm_mma<<<g2,256,GSM>>>(wh+W1,0,0,0,256, ih+IK(3),0,IK(1), 0,ih+IK(5),0,IK(1),
                             pa_b1,0,1, 0,0,0);
    // 7-14: remaining weights + bias concat
    cvtw_k<<<512,256>>>(pa_wc,512,512,0, wh+WC, wl+WC);
    cvtw_k<<<256,256>>>(b1_w,256,256,0, wh+B1, 0);
    cvtw_k<<<256,256>>>(b2_w,256,256,0, wh+B2, 0);
    cvtw_k<<<512,256>>>(fus_w,513,512,0, wh+FU, 0);
    cvtw_k<<<2048,256>>>(b2_w,256,256,gate, wh+B2G, 0);
    cvtw_k<<<2048,256>>>(b1_w,256,256,gate, wh+B1G, 0);
    cvtw_k<<<2048,256>>>(b3_w,256,256,0, wh+B3R, 0);
    bcat_k<<<5,256>>>(b1_b, b2_b, b3_b, bcat);
    // 15-16: x_c -> I1, x_p -> I0
    cvt_k<<<NBCHW/1024,256>>>(x_c, ih+IK(1));
    cvt_k<<<NBCHW/1024,256>>>(x_p, ih+IK(0));
    // 17: merged z1+z2 (2-pass W2, epi addsrc buf[g]) -> I7,I8
    gemm_mma<<<g2,256,GSM>>>(wh+W2,wl+W2,0,0,256, ih+IK(5),0,IK(1), 0,ih+IK(7),0,IK(1),
                             pa_b2,0,2, buf,NBCHW,0);
    // 18: buffer_p (2-pass WC, K512, sigmul x_p) -> I2
    gemm_mma<<<g1,256,GSM>>>(wh+WC,wl+WC,0,0,512, ih+IK(7),ih+IK(8),0, 0,ih+IK(2),0,0,
                             pa_bc,0,3, x_p,0,0);
    // 19: merged Q1+S2 (1-pass, input I2) -> I3,I4 (hi+lo)
    gemm_mma<<<g2,256,GSM>>>(wh+B1,0,0,65536,256, ih+IK(2),0,0, 0,ih+IK(3),il+IK(3),IK(1),
                             bcat,256,0, 0,0,0);
    // 20: merged S1+Q2+v3 (1-pass gated/replicated, input I1) -> I5,I6,I7 (hi+lo)
    gemm_mma<<<g3,256,GSM>>>(wh+B2G,0,65536,524288,256, ih+IK(1),0,0, 0,ih+IK(5),il+IK(5),IK(1),
                             bcat+512,256,0, 0,0,0);
    // 21-22: attention scores
    dim3 gs(HH, BB);
    score_mma<1><<<gs,256,67584>>>(ih+IK(3),il+IK(3), ih+IK(5), Mh, 0);   // Q1,S1 -> M
    score_mma<0><<<gs,256,67584>>>(ih+IK(6),il+IK(6), ih+IK(4), 0, mA);   // Q2,S2 -> mask
    // 23: fused morphology
    morphall_k<<<BB,1024,2*MS*MS*4>>>(mA, vfin);
    // 24: attend (v3 = I7) -> I8
    dim3 ga(2, BB*HH);
    attend_mma<<<ga,256,61440>>>(Mh, ih+IK(7), il+IK(7), ih+IK(8));
    // 25: fusion (1-pass FU, K512: [attend, x_p]) -> out
    gemm_mma<<<g1,256,GSM>>>(wh+FU,0,0,0,512, ih+IK(8),ih+IK(0),0, out,0,0,0,
                             fus_b,0,4, vfin,0,fus_w);
}

// round 12
// speedup vs baseline: 1.0472x; 1.0472x over previous
#include <cuda_runtime.h>
#include <cuda_fp16.h>
#include <math.h>

#define BB 8
#define CC 256
#define HH 128
#define WW 128
#define HWs 16384
#define NBCHW (BB*CC*HWs)
#define MS 134
typedef unsigned long long ull;
typedef unsigned int u32;

__device__ float g_mA[BB*HWs];
__device__ float g_vfinal[BB*HWs];
__device__ float g_gate[BB*CC];
__device__ float g_amean[BB*CC];
__device__ float g_amax[BB*CC];
__device__ float g_bcat[1280];
__device__ __align__(16) __half g_imgh[335544320];
__device__ __align__(16) __half g_imgl[335544320];
__device__ __align__(16) __half g_Mh[16777216];
__device__ __align__(16) __half g_wih[2097152];
__device__ __align__(16) __half g_wil[262144];
#define IK(k) ((long)(k)*33554432L)

__device__ __forceinline__ float sigmoidf_(float x){ return 1.0f/(1.0f+expf(-x)); }
__device__ __forceinline__ u32 smem_u32(const void* p){
    u32 a; asm("{ .reg .u64 t; cvta.to.shared.u64 t, %1; cvt.u32.u64 %0, t; }" : "=r"(a) : "l"(p)); return a; }
__device__ __forceinline__ u32 pack2(float a, float b){
    __half2 t = __floats2half2_rn(a, b); return *(u32*)&t; }
__device__ __forceinline__ void w2(__half* oh, __half* ol, long idx, float a, float b){
    u32 h = pack2(a,b); __half2 hv = *(__half2*)&h;
    ((u32*)oh)[idx>>1] = h;
    if (ol) ((u32*)ol)[idx>>1] = pack2(a-__half2float(hv.x), b-__half2float(hv.y));
}
__device__ __forceinline__ void ldsm4(u32& r0,u32& r1,u32& r2,u32& r3,u32 a){
    asm volatile("ldmatrix.sync.aligned.m8n8.x4.shared.b16 {%0,%1,%2,%3}, [%4];"
        :"=r"(r0),"=r"(r1),"=r"(r2),"=r"(r3):"r"(a)); }
__device__ __forceinline__ void ldsm4t(u32& r0,u32& r1,u32& r2,u32& r3,u32 a){
    asm volatile("ldmatrix.sync.aligned.m8n8.x4.trans.shared.b16 {%0,%1,%2,%3}, [%4];"
        :"=r"(r0),"=r"(r1),"=r"(r2),"=r"(r3):"r"(a)); }
__device__ __forceinline__ void mmah(float* c, const u32* a, const u32* b){
    asm volatile("mma.sync.aligned.m16n8k16.row.col.f32.f16.f16.f32 "
        "{%0,%1,%2,%3},{%4,%5,%6,%7},{%8,%9},{%0,%1,%2,%3};"
        :"+f"(c[0]),"+f"(c[1]),"+f"(c[2]),"+f"(c[3])
        :"r"(a[0]),"r"(a[1]),"r"(a[2]),"r"(a[3]),"r"(b[0]),"r"(b[1])); }
__device__ __forceinline__ void cpa(u32 d, const void* s){
    asm volatile("cp.async.cg.shared.global [%0], [%1], 16;"::"r"(d),"l"(s)); }
__device__ __forceinline__ void cpcommit(){ asm volatile("cp.async.commit_group;":::"memory"); }
__device__ __forceinline__ void cpwait1(){ asm volatile("cp.async.wait_group 1;":::"memory"); }
__device__ __forceinline__ void cpwait0(){ asm volatile("cp.async.wait_group 0;":::"memory"); }

// ---- pool: fp16-hi images only ----
__global__ void pool_k(const float* __restrict__ xp, __half* __restrict__ y1h, __half* __restrict__ y2h){
    long idx = (long)blockIdx.x*256 + threadIdx.x;
    if (idx >= (long)NBCHW) return;
    int w = (int)(idx & 127), h = (int)((idx>>7)&127);
    long base = idx - (long)(h*WW+w);
    float s=0.f, mx=-INFINITY;
    #pragma unroll
    for (int dy=-1;dy<=1;dy++){ int hh=h+dy; if(hh<0||hh>=HH) continue;
        #pragma unroll
        for (int dx=-1;dx<=1;dx++){ int ww=w+dx; if(ww<0||ww>=WW) continue;
            float v = xp[base+hh*WW+ww]; s+=v; mx=fmaxf(mx,v); } }
    y1h[idx]=__float2half_rn(s*(1.f/9.f)); y2h[idx]=__float2half_rn(mx);
}
__global__ void reduce_k(const float* __restrict__ x, float* __restrict__ mean, float* __restrict__ mxo){
    __shared__ float ss[256], sm[256];
    int bc=blockIdx.x, t=threadIdx.x;
    const float* p = x + (long)bc*HWs;
    float s=0.f, m=-INFINITY;
    for (int i=t;i<HWs;i+=256){ float v=p[i]; s+=v; m=fmaxf(m,v); }
    ss[t]=s; sm[t]=m; __syncthreads();
    for (int o=128;o>0;o>>=1){ if (t<o){ ss[t]+=ss[t+o]; sm[t]=fmaxf(sm[t],sm[t+o]); } __syncthreads(); }
    if (t==0){ mean[bc]=ss[0]*(1.f/(float)HWs); mxo[bc]=sm[0]; }
}
__global__ void cagate_k(const float* __restrict__ amean, const float* __restrict__ amax,
    const float* __restrict__ aw1, const float* __restrict__ ab1,
    const float* __restrict__ aw2, const float* __restrict__ ab2,
    const float* __restrict__ mw1, const float* __restrict__ mb1,
    const float* __restrict__ mw2, const float* __restrict__ mb2, float* __restrict__ gate){
    __shared__ float ha[16], hm[16];
    int b=blockIdx.x, t=threadIdx.x;
    if (t<16){ float s=ab1[t]; for (int i=0;i<CC;i++) s+=aw1[t*CC+i]*amean[b*CC+i]; ha[t]=fmaxf(s,0.f); }
    else if (t<32){ int u=t-16; float s=mb1[u]; for (int i=0;i<CC;i++) s+=mw1[u*CC+i]*amax[b*CC+i]; hm[u]=fmaxf(s,0.f); }
    __syncthreads();
    float g = ab2[t]+mb2[t];
    #pragma unroll
    for (int k=0;k<16;k++) g += aw2[t*16+k]*ha[k] + mw2[t*16+k]*hm[k];
    gate[b*CC+t] = sigmoidf_(g);
}
__global__ void cvt_k(const float* __restrict__ src, __half* __restrict__ oh){
    long i4 = ((long)blockIdx.x*256 + threadIdx.x)*4;
    float4 v = *(const float4*)(src + i4);
    ((u32*)oh)[i4>>1]     = pack2(v.x, v.y);
    ((u32*)oh)[(i4>>1)+1] = pack2(v.z, v.w);
}
__global__ void cvtw_k(const float* __restrict__ W, int RS, int K, const float* __restrict__ gate,
                       __half* __restrict__ oh, __half* __restrict__ ol){
    int idx = blockIdx.x*256 + threadIdx.x;
    int b = idx/(256*K); int rem = idx - b*256*K; int m = rem/K, k = rem - m*K;
    float v = W[(long)m*RS + k];
    if (gate) v *= gate[b*256 + k];
    __half h = __float2half_rn(v);
    oh[idx] = h;
    if (ol) ol[idx] = __float2half_rn(v - __half2float(h));
}
__global__ void bcat_k(const float* __restrict__ b1, const float* __restrict__ b2,
                       const float* __restrict__ b3, float* __restrict__ o){
    int t = blockIdx.x*256 + threadIdx.x;
    if (t<256) o[t]=b1[t];
    else if (t<512) o[t]=b2[t-256];
    else if (t<768) o[t]=b2[t-512];
    else if (t<1024) o[t]=b1[t-768];
    else if (t<1280) o[t]=b3[t-1024];
}

// ---- HMMA GEMM with batch+group dims: by = g*8 + b ----
// epi: 0 none, 1 relu, 2 add half-image E0[g], 3 sigmoid*E0(fp32), 4 fusion
#define STG 49664u
#define GSM (2*49664)
__global__ void __launch_bounds__(256,1) gemm_mma(
    const __half* __restrict__ Wh, const __half* __restrict__ Wl, long wBS, long wGS, int K,
    const __half* __restrict__ X0h, const __half* __restrict__ X1h, long xGS,
    float* __restrict__ Yf, __half* __restrict__ Yh, __half* __restrict__ Yl, long yGS,
    const float* __restrict__ bias, int biasGS, int epi,
    const void* __restrict__ E0, long e0GS, const float* __restrict__ E1)
{
    extern __shared__ __align__(16) char smem[];
    u32 sm = smem_u32(smem);
    int tid=threadIdx.x, lane=tid&31, wid=tid>>5;
    int n0 = blockIdx.x*128;
    int by = blockIdx.y, b = by & 7, g = by >> 3;
    int wm = (wid&1)*128, wn = (wid>>1)*32;
    int lr = lane&15, lc8 = (lane>>4)*8;
    const __half* WhB = Wh + (long)b*wBS + (long)g*wGS;
    const __half* WlB = Wl ? (Wl + (long)b*wBS + (long)g*wGS) : 0;
    const __half* X0 = X0h + (long)g*xGS;
    const float* biasg = bias + g*biasGS;
    int NC = K>>5;
    float acc[32][4];
    #pragma unroll
    for (int i=0;i<32;i++){ acc[i][0]=0;acc[i][1]=0;acc[i][2]=0;acc[i][3]=0; }
    for (int c=0; c<=NC; c++){
        if (c<NC){
            u32 st = sm + (u32)(c&1)*STG;
            int kb = c*32;
            #pragma unroll
            for (int j=0;j<4;j++){
                int o=tid+256*j, r=o>>2, cb=o&3;
                u32 d = st + (u32)(r*80+cb*16);
                cpa(d, WhB + (size_t)r*K + kb + cb*8);
                if (WlB) cpa(d + 20480u, WlB + (size_t)r*K + kb + cb*8);
            }
            const __half *xh=X0; int kk=kb;
            if (kk>=256){ xh=X1h; kk-=256; }
            #pragma unroll
            for (int j=0;j<2;j++){
                int o=tid+256*j, r=o>>4, cb=o&15;
                size_t s = ((size_t)b*256 + kk + r)*HWs + n0 + cb*8;
                cpa(st + 40960u + (u32)(r*272+cb*16), xh + s);
            }
            cpcommit();
        }
        if (c==0) continue;
        if (c<NC) cpwait1(); else cpwait0();
        __syncthreads();
        u32 sA = sm + (u32)((c-1)&1)*STG;
        #pragma unroll
        for (int ks=0; ks<32; ks+=16){
            u32 bh[4][2];
            #pragma unroll
            for (int pr=0; pr<2; pr++){
                u32 off = (u32)((ks+lr)*272 + (wn+pr*16+lc8)*2);
                ldsm4t(bh[pr*2][0],bh[pr*2][1],bh[pr*2+1][0],bh[pr*2+1][1], sA+40960u+off);
            }
            #pragma unroll
            for (int mt=0; mt<8; mt++){
                u32 ah[4], al[4];
                u32 off = (u32)((wm+mt*16+lr)*80 + (ks+lc8)*2);
                ldsm4(ah[0],ah[1],ah[2],ah[3], sA+off);
                if (WlB) ldsm4(al[0],al[1],al[2],al[3], sA+20480u+off);
                #pragma unroll
                for (int nt=0; nt<4; nt++){
                    float* cc = acc[mt*4+nt];
                    mmah(cc, ah, bh[nt]);
                    if (WlB) mmah(cc, al, bh[nt]);
                }
            }
        }
        __syncthreads();
    }
    __half* Yhg = Yh ? Yh + (long)g*yGS : 0;
    __half* Ylg = Yl ? Yl + (long)g*yGS : 0;
    #pragma unroll
    for (int mt=0; mt<8; mt++){
        #pragma unroll
        for (int nt=0; nt<4; nt++){
            float* cc = acc[mt*4+nt];
            int n = n0 + wn + nt*8 + (lane&3)*2;
            #pragma unroll
            for (int hlf=0; hlf<2; hlf++){
                int m = wm + mt*16 + (lane>>2) + hlf*8;
                float v0 = cc[hlf*2] + biasg[m], v1 = cc[hlf*2+1] + biasg[m];
                long yb = ((long)b*CC + m)*HWs + n;
                if (epi==1){ v0=fmaxf(v0,0.f); v1=fmaxf(v1,0.f); }
                else if (epi==2){
                    const __half* eh = (const __half*)E0 + (long)g*e0GS + yb;
                    u32 pv = *(const u32*)eh; __half2 h2v = *(__half2*)&pv;
                    v0 += __half2float(h2v.x); v1 += __half2float(h2v.y);
                }
                else if (epi==3){ const float* ef=(const float*)E0;
                    v0=sigmoidf_(v0)*ef[yb]; v1=sigmoidf_(v1)*ef[yb+1]; }
                else if (epi==4){ float wl=E1[(long)m*513+512]; long eb=(long)b*HWs+n;
                    const float* ef=(const float*)E0;
                    v0+=wl*ef[eb]; v1+=wl*ef[eb+1]; }
                if (Yf){ float2 st={v0,v1}; *(float2*)(Yf+yb)=st; }
                else   w2(Yhg, Ylg, yb, v0, v1);
            }
        }
    }
}

// ---- HMMA score (A=Q 2-pass, B=S hi); softmax over j ----
template<int WRITE_M>
__global__ void __launch_bounds__(256,1) score_mma(
    const __half* __restrict__ Qh, const __half* __restrict__ Ql,
    const __half* __restrict__ Sh,
    __half* __restrict__ Mh, float* __restrict__ mOut)
{
    extern __shared__ __align__(16) char smem[];
    u32 sm = smem_u32(smem);
    float* smE = (float*)smem;
    int tid=threadIdx.x, lane=tid&31, wid=tid>>5;
    int h = blockIdx.x, b = blockIdx.y;
    int wm=(wid&1)*64, wn=(wid>>1)*32;
    int lr=lane&15, lc8=(lane>>4)*8;
    float acc[16][4];
    #pragma unroll
    for (int i=0;i<16;i++){ acc[i][0]=0;acc[i][1]=0;acc[i][2]=0;acc[i][3]=0; }
    for (int c=0;c<=8;c++){
        if (c<8){
            u32 st = sm + (u32)(c&1)*26112u;
            int kb = c*32;
            #pragma unroll
            for (int j=0;j<2;j++){
                int o = tid + 256*j, r = o>>4, cb = o&15;
                size_t s = ((size_t)(b*256 + kb + r))*HWs + h*128 + cb*8;
                u32 d = st + (u32)(r*272 + cb*16);
                cpa(d, Qh+s); cpa(d+8704u, Ql+s); cpa(d+17408u, Sh+s);
            }
            cpcommit();
        }
        if (c==0) continue;
        if (c<8) cpwait1(); else cpwait0();
        __syncthreads();
        u32 sA = sm + (u32)((c-1)&1)*26112u;
        #pragma unroll
        for (int ks=0;ks<32;ks+=16){
            u32 bh[4][2];
            #pragma unroll
            for (int pr=0;pr<2;pr++){
                u32 off = (u32)((ks+lr)*272 + (wn+pr*16+lc8)*2);
                ldsm4t(bh[pr*2][0],bh[pr*2][1],bh[pr*2+1][0],bh[pr*2+1][1], sA+17408u+off);
            }
            #pragma unroll
            for (int mt=0;mt<4;mt++){
                u32 r0,r1,r2,r3,q0,q1,q2,q3;
                u32 off = (u32)((ks+lr)*272 + (wm+mt*16+lc8)*2);
                ldsm4t(r0,r1,r2,r3, sA+off);
                ldsm4t(q0,q1,q2,q3, sA+8704u+off);
                u32 ah[4]={r0,r2,r1,r3}, al[4]={q0,q2,q1,q3};
                #pragma unroll
                for (int nt=0;nt<4;nt++){
                    float* cc = acc[mt*4+nt];
                    mmah(cc, ah, bh[nt]); mmah(cc, al, bh[nt]);
                }
            }
        }
        __syncthreads();
    }
    #pragma unroll
    for (int mt=0;mt<4;mt++)
        #pragma unroll
        for (int nt=0;nt<4;nt++){
            float* cc = acc[mt*4+nt];
            int n = wn + nt*8 + (lane&3)*2;
            #pragma unroll
            for (int hlf=0;hlf<2;hlf++){
                int m = wm + mt*16 + (lane>>2) + hlf*8;
                smE[m*132+n] = cc[hlf*2]; smE[m*132+n+1] = cc[hlf*2+1];
            }
        }
    __syncthreads();
    int row = tid>>1, c0 = (tid&1)*64;
    float* rp = smE + row*132 + c0;
    float mx = -INFINITY;
    for (int j=0;j<64;j++) mx = fmaxf(mx, rp[j]);
    mx = fmaxf(mx, __shfl_xor_sync(0xffffffffu, mx, 1));
    float sum = 0.f;
    for (int j=0;j<64;j++){ float e = expf(rp[j]-mx); rp[j] = e; sum += e; }
    sum += __shfl_xor_sync(0xffffffffu, sum, 1);
    float inv = 1.f/sum;
    if (WRITE_M){
        long base = ((long)(b*128+h)*128 + row)*128 + c0;
        for (int j=0;j<64;j+=2)
            ((u32*)Mh)[(base+j)>>1] = pack2(rp[j]*inv, rp[j+1]*inv);
    } else {
        for (int j=0;j<64;j++) rp[j] *= inv;
        __syncthreads();
        if (tid < 128){
            float t = 0.f;
            for (int i=0;i<128;i++) t += smE[i*132+tid];
            mOut[(long)b*HWs + h*128 + tid] = (t>0.1f)?0.f:1.f;
        }
    }
}

// ---- HMMA attend (1-pass: A=v3 hi, B=M hi) ----
// stage: Vh 0 (10240), Mh 10240 (10240); stage=20480, dyn=40960
__global__ void __launch_bounds__(256,1) attend_mma(
    const __half* __restrict__ Mh,
    const __half* __restrict__ Vh,
    __half* __restrict__ Oh)
{
    extern __shared__ __align__(16) char smem[];
    u32 sm = smem_u32(smem);
    int tid=threadIdx.x, lane=tid&31, wid=tid>>5;
    int c0 = blockIdx.x*128, bh = blockIdx.y, b = bh>>7, h = bh&127;
    int wm=(wid&1)*64, wn=(wid>>1)*32;
    int lr=lane&15, lc8=(lane>>4)*8;
    int tile=lane>>3, lrow=lane&7;
    float acc[16][4];
    #pragma unroll
    for (int i=0;i<16;i++){ acc[i][0]=0;acc[i][1]=0;acc[i][2]=0;acc[i][3]=0; }
    for (int c=0;c<=4;c++){
        if (c<4){
            u32 st = sm + (u32)(c&1)*20480u;
            int kb = c*32;
            #pragma unroll
            for (int j=0;j<2;j++){
                int o = tid + 256*j, r = o>>2, cb = o&3;
                u32 d = st + (u32)(r*80 + cb*16);
                size_t s = ((size_t)(b*256 + c0 + r))*HWs + h*128 + kb + cb*8;
                cpa(d, Vh+s);
                size_t s2 = (((size_t)(b*128+h)*128 + r))*128 + kb + cb*8;
                cpa(d+10240u, Mh+s2);
            }
            cpcommit();
        }
        if (c==0) continue;
        if (c<4) cpwait1(); else cpwait0();
        __syncthreads();
        u32 sA = sm + (u32)((c-1)&1)*20480u;
        #pragma unroll
        for (int ks=0;ks<32;ks+=16){
            u32 bh_[4][2];
            #pragma unroll
            for (int pr=0;pr<2;pr++){
                u32 off = (u32)(((wn+pr*16+(tile>>1)*8+lrow)*40 + ks + (tile&1)*8)*2);
                u32 r0,r1,r2,r3;
                ldsm4(r0,r1,r2,r3, sA+10240u+off);
                bh_[pr*2][0]=r0; bh_[pr*2][1]=r1; bh_[pr*2+1][0]=r2; bh_[pr*2+1][1]=r3;
            }
            #pragma unroll
            for (int mt=0;mt<4;mt++){
                u32 ah[4];
                u32 off = (u32)((wm+mt*16+lr)*80 + (ks+lc8)*2);
                ldsm4(ah[0],ah[1],ah[2],ah[3], sA+off);
                #pragma unroll
                for (int nt=0;nt<4;nt++)
                    mmah(acc[mt*4+nt], ah, bh_[nt]);
            }
        }
        __syncthreads();
    }
    #pragma unroll
    for (int mt=0;mt<4;mt++)
        #pragma unroll
        for (int nt=0;nt<4;nt++){
            float* cc = acc[mt*4+nt];
            int n = wn + nt*8 + (lane&3)*2;
            #pragma unroll
            for (int hlf=0;hlf<2;hlf++){
                int m = wm + mt*16 + (lane>>2) + hlf*8;
                long idx = ((long)(b*256 + c0 + m))*HWs + h*128 + n;
                ((u32*)Oh)[idx>>1] = pack2(cc[hlf*2], cc[hlf*2+1]);
            }
        }
}

// ---- fused morphology ----
__device__ void morp(float* dst, const float* src, int r, int erode, int D, int t, int NT){
    int r2 = r*r;
    for (int i=t; i<D*D; i+=NT){
        int h = i/D, w = i - h*D;
        float res = erode ? 1.f : 0.f;
        for (int dy=-r; dy<=r; dy++) for (int dx=-r; dx<=r; dx++){
            if (dy*dy+dx*dx > r2) continue;
            int hh=h+dy, ww=w+dx;
            float v = (hh>=0&&hh<D&&ww>=0&&ww<D) ? src[hh*MS+ww] : 0.f;
            if (erode){ if (v<0.5f) res=0.f; } else if (v>0.5f) res=1.f;
        }
        dst[h*MS+w] = res;
    }
}
__global__ void morphall_k(const float* __restrict__ src, float* __restrict__ dst){
    extern __shared__ float sA[];
    float* A = sA; float* B = sA + MS*MS;
    int b = blockIdx.x, t = threadIdx.x, NT = blockDim.x;
    for (int i=t;i<MS*MS;i+=NT){ A[i]=0.f; B[i]=0.f; }
    __syncthreads();
    for (int i=t;i<HWs;i+=NT){ int h=i>>7, w=i&127; A[h*MS+w]=src[(long)b*HWs+i]; }
    __syncthreads();
    morp(B,A,2,1,128,t,NT); __syncthreads();
    morp(A,B,2,0,128,t,NT); __syncthreads();
    morp(B,A,1,0,128,t,NT); __syncthreads();
    morp(A,B,1,1,128,t,NT); __syncthreads();
    for (int i=t;i<MS*MS;i+=NT){
        int h=i/MS, w=i-h*MS;
        float v = 0.f;
        if (h>=3 && h<131 && w>=3 && w<131) v = A[(h-3)*MS + (w-3)];
        B[i] = v;
    }
    __syncthreads();
    morp(A,B,3,0,MS,t,NT); __syncthreads();
    morp(B,A,3,1,MS,t,NT); __syncthreads();
    for (int i=t;i<HWs;i+=NT){ int h=i>>7, w=i&127; dst[(long)b*HWs+i] = 1.f - B[(h+3)*MS + (w+3)]; }
}

extern "C" void kernel_launch(void* const* d_in, const int* in_sizes, int n_in,
                              void* d_out, int out_size) {
    const float* x_p=(const float*)d_in[0];  const float* x_c=(const float*)d_in[1];
    const float* pa_w1=(const float*)d_in[2];const float* pa_b1=(const float*)d_in[3];
    const float* pa_w2=(const float*)d_in[4];const float* pa_b2=(const float*)d_in[5];
    const float* pa_wc=(const float*)d_in[6];const float* pa_bc=(const float*)d_in[7];
    const float* ca_aw1=(const float*)d_in[8];const float* ca_ab1=(const float*)d_in[9];
    const float* ca_aw2=(const float*)d_in[10];const float* ca_ab2=(const float*)d_in[11];
    const float* ca_mw1=(const float*)d_in[12];const float* ca_mb1=(const float*)d_in[13];
    const float* ca_mw2=(const float*)d_in[14];const float* ca_mb2=(const float*)d_in[15];
    const float* b1_w=(const float*)d_in[16];const float* b1_b=(const float*)d_in[17];
    const float* b2_w=(const float*)d_in[18];const float* b2_b=(const float*)d_in[19];
    const float* b3_w=(const float*)d_in[20];const float* b3_b=(const float*)d_in[21];
    const float* fus_w=(const float*)d_in[22];const float* fus_b=(const float*)d_in[23];
    float* out=(float*)d_out;

    float *gate,*amean,*amax,*mA,*vfin,*bcat;
    __half *ih,*il,*wh,*wl,*Mh;
    cudaGetSymbolAddress((void**)&gate,g_gate);
    cudaGetSymbolAddress((void**)&amean,g_amean); cudaGetSymbolAddress((void**)&amax,g_amax);
    cudaGetSymbolAddress((void**)&mA,g_mA);
    cudaGetSymbolAddress((void**)&vfin,g_vfinal);
    cudaGetSymbolAddress((void**)&bcat,g_bcat);
    cudaGetSymbolAddress((void**)&ih,g_imgh); cudaGetSymbolAddress((void**)&il,g_imgl);
    cudaGetSymbolAddress((void**)&wh,g_wih);  cudaGetSymbolAddress((void**)&wl,g_wil);
    cudaGetSymbolAddress((void**)&Mh,g_Mh);
    cudaFuncSetAttribute(gemm_mma, cudaFuncAttributeMaxDynamicSharedMemorySize, GSM);
    cudaFuncSetAttribute(score_mma<1>, cudaFuncAttributeMaxDynamicSharedMemorySize, 67584);
    cudaFuncSetAttribute(score_mma<0>, cudaFuncAttributeMaxDynamicSharedMemorySize, 67584);
    cudaFuncSetAttribute(attend_mma, cudaFuncAttributeMaxDynamicSharedMemorySize, 40960);
    cudaFuncSetAttribute(morphall_k, cudaFuncAttributeMaxDynamicSharedMemorySize, 2*MS*MS*4);

    const long W1=0, W2=65536, WC=131072, B1=262144, B2=327680, FU=393216;
    const long B2G=524288, B1G=1048576, B3R=1572864;

    // pool (y1h->I3, y2h->I4)
    pool_k<<<NBCHW/256,256>>>(x_p, ih+IK(3), ih+IK(4));
    reduce_k<<<BB*CC,256>>>(x_c, amean, amax);
    cagate_k<<<BB,256>>>(amean,amax,ca_aw1,ca_ab1,ca_aw2,ca_ab2,ca_mw1,ca_mb1,ca_mw2,ca_mb2,gate);
    // all weights 1-pass
    cvtw_k<<<256,256>>>(pa_w1,256,256,0, wh+W1, 0);
    cvtw_k<<<256,256>>>(pa_w2,256,256,0, wh+W2, 0);
    cvtw_k<<<512,256>>>(pa_wc,512,512,0, wh+WC, 0);
    cvtw_k<<<256,256>>>(b1_w,256,256,0, wh+B1, 0);
    cvtw_k<<<512,256>>>(fus_w,513,512,0, wh+FU, 0);
    cvtw_k<<<2048,256>>>(b2_w,256,256,gate, wh+B2G, 0);
    cvtw_k<<<2048,256>>>(b1_w,256,256,gate, wh+B1G, 0);
    cvtw_k<<<2048,256>>>(b3_w,256,256,0, wh+B3R, 0);
    bcat_k<<<5,256>>>(b1_b, b2_b, b3_b, bcat);
    cvt_k<<<NBCHW/1024,256>>>(x_c, ih+IK(1));
    cvt_k<<<NBCHW/1024,256>>>(x_p, ih+IK(0));

    dim3 g2(128,16), g1(128,8), g3(128,24);
    // merged h1+h2 (relu, 1-pass W1) -> I5,I6
    gemm_mma<<<g2,256,GSM>>>(wh+W1,0,0,0,256, ih+IK(3),0,IK(1), 0,ih+IK(5),0,IK(1),
                             pa_b1,0,1, 0,0,0);
    // merged z1+z2 (1-pass W2, epi=2 add half image y[g]) -> I7,I8
    gemm_mma<<<g2,256,GSM>>>(wh+W2,0,0,0,256, ih+IK(5),0,IK(1), 0,ih+IK(7),0,IK(1),
                             pa_b2,0,2, ih+IK(3),IK(1),0);
    // buffer_p (1-pass WC, K512, sigmul x_p fp32) -> I2
    gemm_mma<<<g1,256,GSM>>>(wh+WC,0,0,0,512, ih+IK(7),ih+IK(8),0, 0,ih+IK(2),0,0,
                             pa_bc,0,3, x_p,0,0);
    // merged Q1+S2 (1-pass B1/B2, input I2) -> I3,I4 (hi+lo for Q1)
    gemm_mma<<<g2,256,GSM>>>(wh+B1,0,0,65536,256, ih+IK(2),0,0, 0,ih+IK(3),il+IK(3),IK(1),
                             bcat,256,0, 0,0,0);
    // merged S1+Q2+v3 (1-pass gated b2g,b1g,b3 rep, input I1) -> I5,I6,I7 (hi+lo)
    gemm_mma<<<g3,256,GSM>>>(wh+B2G,0,65536,524288,256, ih+IK(1),0,0, 0,ih+IK(5),il+IK(5),IK(1),
                             bcat+512,256,0, 0,0,0);
    // attention scores
    dim3 gs(HH, BB);
    score_mma<1><<<gs,256,67584>>>(ih+IK(3),il+IK(3), ih+IK(5), Mh, 0);   // Q1,S1 -> M
    score_mma<0><<<gs,256,67584>>>(ih+IK(6),il+IK(6), ih+IK(4), 0, mA);   // Q2,S2 -> mask
    // fused morphology
    morphall_k<<<BB,1024,2*MS*MS*4>>>(mA, vfin);
    // attend (1-pass, v3 = I7 hi) -> I8
    dim3 ga(2, BB*HH);
    attend_mma<<<ga,256,40960>>>(Mh, ih+IK(7), ih+IK(8));
    // fusion (1-pass FU, K512: [attend, x_p]) -> out
    gemm_mma<<<g1,256,GSM>>>(wh+FU,0,0,0,512, ih+IK(8),ih+IK(0),0, out,0,0,0,
                             fus_b,0,4, vfin,0,fus_w);
}

// round 14
// speedup vs baseline: 1.2599x; 1.2031x over previous
#include <cuda_runtime.h>
#include <cuda_fp16.h>
#include <math.h>

#define BB 8
#define CC 256
#define HH 128
#define WW 128
#define HWs 16384
#define NBCHW (BB*CC*HWs)
#define MS 134
typedef unsigned long long ull;
typedef unsigned int u32;

__device__ float g_mA[BB*HWs];
__device__ float g_vfinal[BB*HWs];
__device__ float g_gate[BB*CC];
__device__ float g_amean[BB*CC];
__device__ float g_amax[BB*CC];
__device__ float g_bcat[1280];
__device__ __align__(16) __half g_imgh[335544320];
__device__ __align__(16) __half g_imgl[335544320];
__device__ __align__(16) __half g_Mh[16777216];
__device__ __align__(16) __half g_wih[2097152];
#define IK(k) ((long)(k)*33554432L)

__device__ __forceinline__ float sigmoidf_(float x){ return 1.0f/(1.0f+expf(-x)); }
__device__ __forceinline__ u32 smem_u32(const void* p){
    u32 a; asm("{ .reg .u64 t; cvta.to.shared.u64 t, %1; cvt.u32.u64 %0, t; }" : "=r"(a) : "l"(p)); return a; }
__device__ __forceinline__ u32 pack2(float a, float b){
    __half2 t = __floats2half2_rn(a, b); return *(u32*)&t; }
__device__ __forceinline__ void w2(__half* oh, __half* ol, long idx, float a, float b){
    u32 h = pack2(a,b); __half2 hv = *(__half2*)&h;
    ((u32*)oh)[idx>>1] = h;
    if (ol) ((u32*)ol)[idx>>1] = pack2(a-__half2float(hv.x), b-__half2float(hv.y));
}
__device__ __forceinline__ void ldsm4(u32& r0,u32& r1,u32& r2,u32& r3,u32 a){
    asm volatile("ldmatrix.sync.aligned.m8n8.x4.shared.b16 {%0,%1,%2,%3}, [%4];"
        :"=r"(r0),"=r"(r1),"=r"(r2),"=r"(r3):"r"(a)); }
__device__ __forceinline__ void ldsm4t(u32& r0,u32& r1,u32& r2,u32& r3,u32 a){
    asm volatile("ldmatrix.sync.aligned.m8n8.x4.trans.shared.b16 {%0,%1,%2,%3}, [%4];"
        :"=r"(r0),"=r"(r1),"=r"(r2),"=r"(r3):"r"(a)); }
__device__ __forceinline__ void mmah(float* c, const u32* a, const u32* b){
    asm volatile("mma.sync.aligned.m16n8k16.row.col.f32.f16.f16.f32 "
        "{%0,%1,%2,%3},{%4,%5,%6,%7},{%8,%9},{%0,%1,%2,%3};"
        :"+f"(c[0]),"+f"(c[1]),"+f"(c[2]),"+f"(c[3])
        :"r"(a[0]),"r"(a[1]),"r"(a[2]),"r"(a[3]),"r"(b[0]),"r"(b[1])); }
__device__ __forceinline__ void cpa(u32 d, const void* s){
    asm volatile("cp.async.cg.shared.global [%0], [%1], 16;"::"r"(d),"l"(s)); }
__device__ __forceinline__ void cpcommit(){ asm volatile("cp.async.commit_group;":::"memory"); }
__device__ __forceinline__ void cpwait2(){ asm volatile("cp.async.wait_group 2;":::"memory"); }
__device__ __forceinline__ void cpwait1(){ asm volatile("cp.async.wait_group 1;":::"memory"); }
__device__ __forceinline__ void cpwait0(){ asm volatile("cp.async.wait_group 0;":::"memory"); }

__global__ void pool_k(const float* __restrict__ xp, __half* __restrict__ y1h, __half* __restrict__ y2h){
    long idx = (long)blockIdx.x*256 + threadIdx.x;
    if (idx >= (long)NBCHW) return;
    int w = (int)(idx & 127), h = (int)((idx>>7)&127);
    long base = idx - (long)(h*WW+w);
    float s=0.f, mx=-INFINITY;
    #pragma unroll
    for (int dy=-1;dy<=1;dy++){ int hh=h+dy; if(hh<0||hh>=HH) continue;
        #pragma unroll
        for (int dx=-1;dx<=1;dx++){ int ww=w+dx; if(ww<0||ww>=WW) continue;
            float v = xp[base+hh*WW+ww]; s+=v; mx=fmaxf(mx,v); } }
    y1h[idx]=__float2half_rn(s*(1.f/9.f)); y2h[idx]=__float2half_rn(mx);
}
__global__ void reduce_k(const float* __restrict__ x, float* __restrict__ mean, float* __restrict__ mxo){
    __shared__ float ss[256], sm[256];
    int bc=blockIdx.x, t=threadIdx.x;
    const float* p = x + (long)bc*HWs;
    float s=0.f, m=-INFINITY;
    for (int i=t;i<HWs;i+=256){ float v=p[i]; s+=v; m=fmaxf(m,v); }
    ss[t]=s; sm[t]=m; __syncthreads();
    for (int o=128;o>0;o>>=1){ if (t<o){ ss[t]+=ss[t+o]; sm[t]=fmaxf(sm[t],sm[t+o]); } __syncthreads(); }
    if (t==0){ mean[bc]=ss[0]*(1.f/(float)HWs); mxo[bc]=sm[0]; }
}
__global__ void cagate_k(const float* __restrict__ amean, const float* __restrict__ amax,
    const float* __restrict__ aw1, const float* __restrict__ ab1,
    const float* __restrict__ aw2, const float* __restrict__ ab2,
    const float* __restrict__ mw1, const float* __restrict__ mb1,
    const float* __restrict__ mw2, const float* __restrict__ mb2, float* __restrict__ gate){
    __shared__ float ha[16], hm[16];
    int b=blockIdx.x, t=threadIdx.x;
    if (t<16){ float s=ab1[t]; for (int i=0;i<CC;i++) s+=aw1[t*CC+i]*amean[b*CC+i]; ha[t]=fmaxf(s,0.f); }
    else if (t<32){ int u=t-16; float s=mb1[u]; for (int i=0;i<CC;i++) s+=mw1[u*CC+i]*amax[b*CC+i]; hm[u]=fmaxf(s,0.f); }
    __syncthreads();
    float g = ab2[t]+mb2[t];
    #pragma unroll
    for (int k=0;k<16;k++) g += aw2[t*16+k]*ha[k] + mw2[t*16+k]*hm[k];
    gate[b*CC+t] = sigmoidf_(g);
}
__global__ void cvt_k(const float* __restrict__ src, __half* __restrict__ oh){
    long i4 = ((long)blockIdx.x*256 + threadIdx.x)*4;
    float4 v = *(const float4*)(src + i4);
    ((u32*)oh)[i4>>1]     = pack2(v.x, v.y);
    ((u32*)oh)[(i4>>1)+1] = pack2(v.z, v.w);
}
__global__ void cvtw_k(const float* __restrict__ W, int RS, int K, const float* __restrict__ gate,
                       __half* __restrict__ oh){
    int idx = blockIdx.x*256 + threadIdx.x;
    int b = idx/(256*K); int rem = idx - b*256*K; int m = rem/K, k = rem - m*K;
    float v = W[(long)m*RS + k];
    if (gate) v *= gate[b*256 + k];
    oh[idx] = __float2half_rn(v);
}
__global__ void bcat_k(const float* __restrict__ b1, const float* __restrict__ b2,
                       const float* __restrict__ b3, float* __restrict__ o){
    int t = blockIdx.x*256 + threadIdx.x;
    if (t<256) o[t]=b1[t];
    else if (t<512) o[t]=b2[t-256];
    else if (t<768) o[t]=b2[t-512];
    else if (t<1024) o[t]=b1[t-768];
    else if (t<1280) o[t]=b3[t-1024];
}

// ---- HMMA GEMM 1-pass, 3-stage cp.async, batch+group dims: by = g*8 + b ----
#define STG 29184u
#define GSM (3*29184)
__global__ void __launch_bounds__(256,1) gemm_mma(
    const __half* __restrict__ Wh, long wBS, long wGS, int K,
    const __half* __restrict__ X0h, const __half* __restrict__ X1h, long xGS,
    float* __restrict__ Yf, __half* __restrict__ Yh, __half* __restrict__ Yl, long yGS,
    const float* __restrict__ bias, int biasGS, int epi,
    const void* __restrict__ E0, long e0GS, const float* __restrict__ E1)
{
    extern __shared__ __align__(16) char smem[];
    u32 sm = smem_u32(smem);
    int tid=threadIdx.x, lane=tid&31, wid=tid>>5;
    int n0 = blockIdx.x*128;
    int by = blockIdx.y, b = by & 7, g = by >> 3;
    int wm = (wid&1)*128, wn = (wid>>1)*32;
    int lr = lane&15, lc8 = (lane>>4)*8;
    const __half* WhB = Wh + (long)b*wBS + (long)g*wGS;
    const __half* X0 = X0h + (long)g*xGS;
    const float* biasg = bias + g*biasGS;
    int NC = K>>5;
    float acc[32][4];
    #pragma unroll
    for (int i=0;i<32;i++){ acc[i][0]=0;acc[i][1]=0;acc[i][2]=0;acc[i][3]=0; }
    for (int c=0; c<NC+2; c++){
        __syncthreads();   // buffer c%3 free (compute c-3 done by all warps)
        if (c<NC){
            u32 st = sm + (u32)(c%3)*STG;
            int kb = c*32;
            #pragma unroll
            for (int j=0;j<4;j++){
                int o=tid+256*j, r=o>>2, cb=o&3;
                cpa(st + (u32)(r*80+cb*16), WhB + (size_t)r*K + kb + cb*8);
            }
            const __half *xh=X0; int kk=kb;
            if (kk>=256){ xh=X1h; kk-=256; }
            #pragma unroll
            for (int j=0;j<2;j++){
                int o=tid+256*j, r=o>>4, cb=o&15;
                size_t s = ((size_t)b*256 + kk + r)*HWs + n0 + cb*8;
                cpa(st + 20480u + (u32)(r*272+cb*16), xh + s);
            }
            cpcommit();
        }
        if (c<2) continue;
        int cc = c-2;
        int iw = ((c<NC-1)?c:(NC-1)) - cc;
        if (iw>=2) cpwait2(); else if (iw==1) cpwait1(); else cpwait0();
        __syncthreads();
        u32 sA = sm + (u32)(cc%3)*STG;
        #pragma unroll
        for (int ks=0; ks<32; ks+=16){
            u32 bh[4][2];
            #pragma unroll
            for (int pr=0; pr<2; pr++){
                u32 off = (u32)((ks+lr)*272 + (wn+pr*16+lc8)*2);
                ldsm4t(bh[pr*2][0],bh[pr*2][1],bh[pr*2+1][0],bh[pr*2+1][1], sA+20480u+off);
            }
            #pragma unroll
            for (int mt=0; mt<8; mt++){
                u32 ah[4];
                u32 off = (u32)((wm+mt*16+lr)*80 + (ks+lc8)*2);
                ldsm4(ah[0],ah[1],ah[2],ah[3], sA+off);
                #pragma unroll
                for (int nt=0; nt<4; nt++)
                    mmah(acc[mt*4+nt], ah, bh[nt]);
            }
        }
    }
    __half* Yhg = Yh ? Yh + (long)g*yGS : 0;
    __half* Ylg = Yl ? Yl + (long)g*yGS : 0;
    #pragma unroll
    for (int mt=0; mt<8; mt++){
        #pragma unroll
        for (int nt=0; nt<4; nt++){
            float* cc = acc[mt*4+nt];
            int n = n0 + wn + nt*8 + (lane&3)*2;
            #pragma unroll
            for (int hlf=0; hlf<2; hlf++){
                int m = wm + mt*16 + (lane>>2) + hlf*8;
                float v0 = cc[hlf*2] + biasg[m], v1 = cc[hlf*2+1] + biasg[m];
                long yb = ((long)b*CC + m)*HWs + n;
                if (epi==1){ v0=fmaxf(v0,0.f); v1=fmaxf(v1,0.f); }
                else if (epi==2){
                    const __half* eh = (const __half*)E0 + (long)g*e0GS + yb;
                    u32 pv = *(const u32*)eh; __half2 h2v = *(__half2*)&pv;
                    v0 += __half2float(h2v.x); v1 += __half2float(h2v.y);
                }
                else if (epi==3){ const float* ef=(const float*)E0;
                    v0=sigmoidf_(v0)*ef[yb]; v1=sigmoidf_(v1)*ef[yb+1]; }
                else if (epi==4){ float wl=E1[(long)m*513+512]; long eb=(long)b*HWs+n;
                    const float* ef=(const float*)E0;
                    v0+=wl*ef[eb]; v1+=wl*ef[eb+1]; }
                if (Yf){ float2 st={v0,v1}; *(float2*)(Yf+yb)=st; }
                else   w2(Yhg, Ylg, yb, v0, v1);
            }
        }
    }
}

// ---- HMMA score (A=Q 2-pass, B=S hi); softmax over j ----
template<int WRITE_M>
__global__ void __launch_bounds__(256,1) score_mma(
    const __half* __restrict__ Qh, const __half* __restrict__ Ql,
    const __half* __restrict__ Sh,
    __half* __restrict__ Mh, float* __restrict__ mOut)
{
    extern __shared__ __align__(16) char smem[];
    u32 sm = smem_u32(smem);
    float* smE = (float*)smem;
    int tid=threadIdx.x, lane=tid&31, wid=tid>>5;
    int h = blockIdx.x, b = blockIdx.y;
    int wm=(wid&1)*64, wn=(wid>>1)*32;
    int lr=lane&15, lc8=(lane>>4)*8;
    float acc[16][4];
    #pragma unroll
    for (int i=0;i<16;i++){ acc[i][0]=0;acc[i][1]=0;acc[i][2]=0;acc[i][3]=0; }
    for (int c=0;c<=8;c++){
        if (c<8){
            u32 st = sm + (u32)(c&1)*26112u;
            int kb = c*32;
            #pragma unroll
            for (int j=0;j<2;j++){
                int o = tid + 256*j, r = o>>4, cb = o&15;
                size_t s = ((size_t)(b*256 + kb + r))*HWs + h*128 + cb*8;
                u32 d = st + (u32)(r*272 + cb*16);
                cpa(d, Qh+s); cpa(d+8704u, Ql+s); cpa(d+17408u, Sh+s);
            }
            cpcommit();
        }
        if (c==0) continue;
        if (c<8) cpwait1(); else cpwait0();
        __syncthreads();
        u32 sA = sm + (u32)((c-1)&1)*26112u;
        #pragma unroll
        for (int ks=0;ks<32;ks+=16){
            u32 bh[4][2];
            #pragma unroll
            for (int pr=0;pr<2;pr++){
                u32 off = (u32)((ks+lr)*272 + (wn+pr*16+lc8)*2);
                ldsm4t(bh[pr*2][0],bh[pr*2][1],bh[pr*2+1][0],bh[pr*2+1][1], sA+17408u+off);
            }
            #pragma unroll
            for (int mt=0;mt<4;mt++){
                u32 r0,r1,r2,r3,q0,q1,q2,q3;
                u32 off = (u32)((ks+lr)*272 + (wm+mt*16+lc8)*2);
                ldsm4t(r0,r1,r2,r3, sA+off);
                ldsm4t(q0,q1,q2,q3, sA+8704u+off);
                u32 ah[4]={r0,r2,r1,r3}, al[4]={q0,q2,q1,q3};
                #pragma unroll
                for (int nt=0;nt<4;nt++){
                    float* cc = acc[mt*4+nt];
                    mmah(cc, ah, bh[nt]); mmah(cc, al, bh[nt]);
                }
            }
        }
        __syncthreads();
    }
    #pragma unroll
    for (int mt=0;mt<4;mt++)
        #pragma unroll
        for (int nt=0;nt<4;nt++){
            float* cc = acc[mt*4+nt];
            int n = wn + nt*8 + (lane&3)*2;
            #pragma unroll
            for (int hlf=0;hlf<2;hlf++){
                int m = wm + mt*16 + (lane>>2) + hlf*8;
                smE[m*132+n] = cc[hlf*2]; smE[m*132+n+1] = cc[hlf*2+1];
            }
        }
    __syncthreads();
    int row = tid>>1, c0 = (tid&1)*64;
    float* rp = smE + row*132 + c0;
    float mx = -INFINITY;
    for (int j=0;j<64;j++) mx = fmaxf(mx, rp[j]);
    mx = fmaxf(mx, __shfl_xor_sync(0xffffffffu, mx, 1));
    float sum = 0.f;
    for (int j=0;j<64;j++){ float e = expf(rp[j]-mx); rp[j] = e; sum += e; }
    sum += __shfl_xor_sync(0xffffffffu, sum, 1);
    float inv = 1.f/sum;
    if (WRITE_M){
        long base = ((long)(b*128+h)*128 + row)*128 + c0;
        for (int j=0;j<64;j+=2)
            ((u32*)Mh)[(base+j)>>1] = pack2(rp[j]*inv, rp[j+1]*inv);
    } else {
        for (int j=0;j<64;j++) rp[j] *= inv;
        __syncthreads();
        if (tid < 128){
            float t = 0.f;
            for (int i=0;i<128;i++) t += smE[i*132+tid];
            mOut[(long)b*HWs + h*128 + tid] = (t>0.1f)?0.f:1.f;
        }
    }
}

// ---- HMMA attend (1-pass) ----
__global__ void __launch_bounds__(256,1) attend_mma(
    const __half* __restrict__ Mh,
    const __half* __restrict__ Vh,
    __half* __restrict__ Oh)
{
    extern __shared__ __align__(16) char smem[];
    u32 sm = smem_u32(smem);
    int tid=threadIdx.x, lane=tid&31, wid=tid>>5;
    int c0 = blockIdx.x*128, bh = blockIdx.y, b = bh>>7, h = bh&127;
    int wm=(wid&1)*64, wn=(wid>>1)*32;
    int lr=lane&15, lc8=(lane>>4)*8;
    int tile=lane>>3, lrow=lane&7;
    float acc[16][4];
    #pragma unroll
    for (int i=0;i<16;i++){ acc[i][0]=0;acc[i][1]=0;acc[i][2]=0;acc[i][3]=0; }
    for (int c=0;c<=4;c++){
        if (c<4){
            u32 st = sm + (u32)(c&1)*20480u;
            int kb = c*32;
            #pragma unroll
            for (int j=0;j<2;j++){
                int o = tid + 256*j, r = o>>2, cb = o&3;
                u32 d = st + (u32)(r*80 + cb*16);
                size_t s = ((size_t)(b*256 + c0 + r))*HWs + h*128 + kb + cb*8;
                cpa(d, Vh+s);
                size_t s2 = (((size_t)(b*128+h)*128 + r))*128 + kb + cb*8;
                cpa(d+10240u, Mh+s2);
            }
            cpcommit();
        }
        if (c==0) continue;
        if (c<4) cpwait1(); else cpwait0();
        __syncthreads();
        u32 sA = sm + (u32)((c-1)&1)*20480u;
        #pragma unroll
        for (int ks=0;ks<32;ks+=16){
            u32 bh_[4][2];
            #pragma unroll
            for (int pr=0;pr<2;pr++){
                u32 off = (u32)(((wn+pr*16+(tile>>1)*8+lrow)*40 + ks + (tile&1)*8)*2);
                u32 r0,r1,r2,r3;
                ldsm4(r0,r1,r2,r3, sA+10240u+off);
                bh_[pr*2][0]=r0; bh_[pr*2][1]=r1; bh_[pr*2+1][0]=r2; bh_[pr*2+1][1]=r3;
            }
            #pragma unroll
            for (int mt=0;mt<4;mt++){
                u32 ah[4];
                u32 off = (u32)((wm+mt*16+lr)*80 + (ks+lc8)*2);
                ldsm4(ah[0],ah[1],ah[2],ah[3], sA+off);
                #pragma unroll
                for (int nt=0;nt<4;nt++)
                    mmah(acc[mt*4+nt], ah, bh_[nt]);
            }
        }
        __syncthreads();
    }
    #pragma unroll
    for (int mt=0;mt<4;mt++)
        #pragma unroll
        for (int nt=0;nt<4;nt++){
            float* cc = acc[mt*4+nt];
            int n = wn + nt*8 + (lane&3)*2;
            #pragma unroll
            for (int hlf=0;hlf<2;hlf++){
                int m = wm + mt*16 + (lane>>2) + hlf*8;
                long idx = ((long)(b*256 + c0 + m))*HWs + h*128 + n;
                ((u32*)Oh)[idx>>1] = pack2(cc[hlf*2], cc[hlf*2+1]);
            }
        }
}

// ---- fused morphology ----
__device__ void morp(float* dst, const float* src, int r, int erode, int D, int t, int NT){
    int r2 = r*r;
    for (int i=t; i<D*D; i+=NT){
        int h = i/D, w = i - h*D;
        float res = erode ? 1.f : 0.f;
        for (int dy=-r; dy<=r; dy++) for (int dx=-r; dx<=r; dx++){
            if (dy*dy+dx*dx > r2) continue;
            int hh=h+dy, ww=w+dx;
            float v = (hh>=0&&hh<D&&ww>=0&&ww<D) ? src[hh*MS+ww] : 0.f;
            if (erode){ if (v<0.5f) res=0.f; } else if (v>0.5f) res=1.f;
        }
        dst[h*MS+w] = res;
    }
}
__global__ void morphall_k(const float* __restrict__ src, float* __restrict__ dst){
    extern __shared__ float sA[];
    float* A = sA; float* B = sA + MS*MS;
    int b = blockIdx.x, t = threadIdx.x, NT = blockDim.x;
    for (int i=t;i<MS*MS;i+=NT){ A[i]=0.f; B[i]=0.f; }
    __syncthreads();
    for (int i=t;i<HWs;i+=NT){ int h=i>>7, w=i&127; A[h*MS+w]=src[(long)b*HWs+i]; }
    __syncthreads();
    morp(B,A,2,1,128,t,NT); __syncthreads();
    morp(A,B,2,0,128,t,NT); __syncthreads();
    morp(B,A,1,0,128,t,NT); __syncthreads();
    morp(A,B,1,1,128,t,NT); __syncthreads();
    for (int i=t;i<MS*MS;i+=NT){
        int h=i/MS, w=i-h*MS;
        float v = 0.f;
        if (h>=3 && h<131 && w>=3 && w<131) v = A[(h-3)*MS + (w-3)];
        B[i] = v;
    }
    __syncthreads();
    morp(A,B,3,0,MS,t,NT); __syncthreads();
    morp(B,A,3,1,MS,t,NT); __syncthreads();
    for (int i=t;i<HWs;i+=NT){ int h=i>>7, w=i&127; dst[(long)b*HWs+i] = 1.f - B[(h+3)*MS + (w+3)]; }
}

extern "C" void kernel_launch(void* const* d_in, const int* in_sizes, int n_in,
                              void* d_out, int out_size) {
    const float* x_p=(const float*)d_in[0];  const float* x_c=(const float*)d_in[1];
    const float* pa_w1=(const float*)d_in[2];const float* pa_b1=(const float*)d_in[3];
    const float* pa_w2=(const float*)d_in[4];const float* pa_b2=(const float*)d_in[5];
    const float* pa_wc=(const float*)d_in[6];const float* pa_bc=(const float*)d_in[7];
    const float* ca_aw1=(const float*)d_in[8];const float* ca_ab1=(const float*)d_in[9];
    const float* ca_aw2=(const float*)d_in[10];const float* ca_ab2=(const float*)d_in[11];
    const float* ca_mw1=(const float*)d_in[12];const float* ca_mb1=(const float*)d_in[13];
    const float* ca_mw2=(const float*)d_in[14];const float* ca_mb2=(const float*)d_in[15];
    const float* b1_w=(const float*)d_in[16];const float* b1_b=(const float*)d_in[17];
    const float* b2_w=(const float*)d_in[18];const float* b2_b=(const float*)d_in[19];
    const float* b3_w=(const float*)d_in[20];const float* b3_b=(const float*)d_in[21];
    const float* fus_w=(const float*)d_in[22];const float* fus_b=(const float*)d_in[23];
    float* out=(float*)d_out;

    float *gate,*amean,*amax,*mA,*vfin,*bcat;
    __half *ih,*il,*wh,*Mh;
    cudaGetSymbolAddress((void**)&gate,g_gate);
    cudaGetSymbolAddress((void**)&amean,g_amean); cudaGetSymbolAddress((void**)&amax,g_amax);
    cudaGetSymbolAddress((void**)&mA,g_mA);
    cudaGetSymbolAddress((void**)&vfin,g_vfinal);
    cudaGetSymbolAddress((void**)&bcat,g_bcat);
    cudaGetSymbolAddress((void**)&ih,g_imgh); cudaGetSymbolAddress((void**)&il,g_imgl);
    cudaGetSymbolAddress((void**)&wh,g_wih);
    cudaGetSymbolAddress((void**)&Mh,g_Mh);
    cudaFuncSetAttribute(gemm_mma, cudaFuncAttributeMaxDynamicSharedMemorySize, GSM);
    cudaFuncSetAttribute(score_mma<1>, cudaFuncAttributeMaxDynamicSharedMemorySize, 67584);
    cudaFuncSetAttribute(score_mma<0>, cudaFuncAttributeMaxDynamicSharedMemorySize, 67584);
    cudaFuncSetAttribute(attend_mma, cudaFuncAttributeMaxDynamicSharedMemorySize, 40960);
    cudaFuncSetAttribute(morphall_k, cudaFuncAttributeMaxDynamicSharedMemorySize, 2*MS*MS*4);

    const long W1=0, W2=65536, WC=131072, B1=262144, B2=327680, FU=393216;
    const long B2G=524288, B1G=1048576, B3R=1572864;
    dim3 g2(128,16), g1(128,8), g3(128,24);
    dim3 gs(HH, BB), ga(2, BB*HH);

    pool_k<<<NBCHW/256,256>>>(x_p, ih+IK(3), ih+IK(4));
    reduce_k<<<BB*CC,256>>>(x_c, amean, amax);
    cagate_k<<<BB,256>>>(amean,amax,ca_aw1,ca_ab1,ca_aw2,ca_ab2,ca_mw1,ca_mb1,ca_mw2,ca_mb2,gate);
    cvtw_k<<<256,256>>>(pa_w1,256,256,0, wh+W1);
    bcat_k<<<5,256>>>(b1_b, b2_b, b3_b, bcat);
    // merged h1+h2 (relu) -> I5,I6  [ncu target]
    gemm_mma<<<g2,256,GSM>>>(wh+W1,0,0,256, ih+IK(3),0,IK(1), 0,ih+IK(5),0,IK(1),
                             pa_b1,0,1, 0,0,0);
    cvtw_k<<<256,256>>>(pa_w2,256,256,0, wh+W2);
    gemm_mma<<<g2,256,GSM>>>(wh+W2,0,0,256, ih+IK(5),0,IK(1), 0,ih+IK(7),0,IK(1),
                             pa_b2,0,2, ih+IK(3),IK(1),0);
    cvtw_k<<<512,256>>>(pa_wc,512,512,0, wh+WC);
    gemm_mma<<<g1,256,GSM>>>(wh+WC,0,0,512, ih+IK(7),ih+IK(8),0, 0,ih+IK(2),0,0,
                             pa_bc,0,3, x_p,0,0);
    cvt_k<<<NBCHW/1024,256>>>(x_c, ih+IK(1));
    cvt_k<<<NBCHW/1024,256>>>(x_p, ih+IK(0));
    cvtw_k<<<256,256>>>(b1_w,256,256,0, wh+B1);
    cvtw_k<<<256,256>>>(b2_w,256,256,0, wh+B2);
    // merged Q1+S2 -> I3,I4 (hi+lo)
    gemm_mma<<<g2,256,GSM>>>(wh+B1,0,65536,256, ih+IK(2),0,0, 0,ih+IK(3),il+IK(3),IK(1),
                             bcat,256,0, 0,0,0);
    cvtw_k<<<2048,256>>>(b2_w,256,256,gate, wh+B2G);
    cvtw_k<<<2048,256>>>(b1_w,256,256,gate, wh+B1G);
    cvtw_k<<<2048,256>>>(b3_w,256,256,0, wh+B3R);
    // merged S1+Q2+v3 (PER-BATCH stride 65536!) -> I5,I6,I7 (hi+lo)
    gemm_mma<<<g3,256,GSM>>>(wh+B2G,65536,524288,256, ih+IK(1),0,0, 0,ih+IK(5),il+IK(5),IK(1),
                             bcat+512,256,0, 0,0,0);
    // scores
    score_mma<1><<<gs,256,67584>>>(ih+IK(3),il+IK(3), ih+IK(5), Mh, 0);
    score_mma<0><<<gs,256,67584>>>(ih+IK(6),il+IK(6), ih+IK(4), 0, mA);
    // morphology
    morphall_k<<<BB,1024,2*MS*MS*4>>>(mA, vfin);
    // attend -> I8
    attend_mma<<<ga,256,40960>>>(Mh, ih+IK(7), ih+IK(8));
    // fusion
    cvtw_k<<<512,256>>>(fus_w,513,512,0, wh+FU);
    gemm_mma<<<g1,256,GSM>>>(wh+FU,0,0,512, ih+IK(8),ih+IK(0),0, out,0,0,0,
                             fus_b,0,4, vfin,0,fus_w);
}

// round 15
// speedup vs baseline: 1.2740x; 1.0112x over previous
#include <cuda_runtime.h>
#include <cuda_fp16.h>
#include <math.h>

#define BB 8
#define CC 256
#define HH 128
#define WW 128
#define HWs 16384
#define NBCHW (BB*CC*HWs)
#define MS 134
typedef unsigned long long ull;
typedef unsigned int u32;

__device__ float g_mA[BB*HWs];
__device__ float g_vfinal[BB*HWs];
__device__ float g_gate[BB*CC];
__device__ float g_amean[BB*CC];
__device__ float g_amax[BB*CC];
__device__ float g_bcat[1280];
__device__ __align__(16) __half g_imgh[335544320];
__device__ __align__(16) __half g_imgl[335544320];
__device__ __align__(16) __half g_Mh[16777216];
__device__ __align__(16) __half g_wih[2097152];
#define IK(k) ((long)(k)*33554432L)

__device__ __forceinline__ float sigmoidf_(float x){ return 1.0f/(1.0f+expf(-x)); }
__device__ __forceinline__ u32 smem_u32(const void* p){
    u32 a; asm("{ .reg .u64 t; cvta.to.shared.u64 t, %1; cvt.u32.u64 %0, t; }" : "=r"(a) : "l"(p)); return a; }
__device__ __forceinline__ u32 pack2(float a, float b){
    __half2 t = __floats2half2_rn(a, b); return *(u32*)&t; }
__device__ __forceinline__ void w2(__half* oh, __half* ol, long idx, float a, float b){
    u32 h = pack2(a,b); __half2 hv = *(__half2*)&h;
    ((u32*)oh)[idx>>1] = h;
    if (ol) ((u32*)ol)[idx>>1] = pack2(a-__half2float(hv.x), b-__half2float(hv.y));
}
__device__ __forceinline__ void ldsm4(u32& r0,u32& r1,u32& r2,u32& r3,u32 a){
    asm volatile("ldmatrix.sync.aligned.m8n8.x4.shared.b16 {%0,%1,%2,%3}, [%4];"
        :"=r"(r0),"=r"(r1),"=r"(r2),"=r"(r3):"r"(a)); }
__device__ __forceinline__ void ldsm4t(u32& r0,u32& r1,u32& r2,u32& r3,u32 a){
    asm volatile("ldmatrix.sync.aligned.m8n8.x4.trans.shared.b16 {%0,%1,%2,%3}, [%4];"
        :"=r"(r0),"=r"(r1),"=r"(r2),"=r"(r3):"r"(a)); }
__device__ __forceinline__ void mmah(float* c, const u32* a, const u32* b){
    asm volatile("mma.sync.aligned.m16n8k16.row.col.f32.f16.f16.f32 "
        "{%0,%1,%2,%3},{%4,%5,%6,%7},{%8,%9},{%0,%1,%2,%3};"
        :"+f"(c[0]),"+f"(c[1]),"+f"(c[2]),"+f"(c[3])
        :"r"(a[0]),"r"(a[1]),"r"(a[2]),"r"(a[3]),"r"(b[0]),"r"(b[1])); }
__device__ __forceinline__ void cpa(u32 d, const void* s){
    asm volatile("cp.async.cg.shared.global [%0], [%1], 16;"::"r"(d),"l"(s)); }
__device__ __forceinline__ void cpcommit(){ asm volatile("cp.async.commit_group;":::"memory"); }
__device__ __forceinline__ void cpwait(int n){
    if (n>=3) asm volatile("cp.async.wait_group 3;":::"memory");
    else if (n==2) asm volatile("cp.async.wait_group 2;":::"memory");
    else if (n==1) asm volatile("cp.async.wait_group 1;":::"memory");
    else asm volatile("cp.async.wait_group 0;":::"memory");
}

// ---- pool: y1h,y2h + x_p image ----
__global__ void pool_k(const float* __restrict__ xp, __half* __restrict__ y1h,
                       __half* __restrict__ y2h, __half* __restrict__ xph){
    long idx = (long)blockIdx.x*256 + threadIdx.x;
    if (idx >= (long)NBCHW) return;
    int w = (int)(idx & 127), h = (int)((idx>>7)&127);
    long base = idx - (long)(h*WW+w);
    float s=0.f, mx=-INFINITY, ctr=0.f;
    #pragma unroll
    for (int dy=-1;dy<=1;dy++){ int hh=h+dy; if(hh<0||hh>=HH) continue;
        #pragma unroll
        for (int dx=-1;dx<=1;dx++){ int ww=w+dx; if(ww<0||ww>=WW) continue;
            float v = xp[base+hh*WW+ww]; s+=v; mx=fmaxf(mx,v);
            if (dy==0&&dx==0) ctr=v; } }
    y1h[idx]=__float2half_rn(s*(1.f/9.f)); y2h[idx]=__float2half_rn(mx);
    xph[idx]=__float2half_rn(ctr);
}
// ---- reduce + x_c image ----
__global__ void reduce_k(const float* __restrict__ x, float* __restrict__ mean,
                         float* __restrict__ mxo, __half* __restrict__ xch){
    __shared__ float ss[256], sm[256];
    int bc=blockIdx.x, t=threadIdx.x;
    const float* p = x + (long)bc*HWs;
    __half* q = xch + (long)bc*HWs;
    float s=0.f, m=-INFINITY;
    for (int i=t;i<HWs;i+=256){ float v=p[i]; s+=v; m=fmaxf(m,v); q[i]=__float2half_rn(v); }
    ss[t]=s; sm[t]=m; __syncthreads();
    for (int o=128;o>0;o>>=1){ if (t<o){ ss[t]+=ss[t+o]; sm[t]=fmaxf(sm[t],sm[t+o]); } __syncthreads(); }
    if (t==0){ mean[bc]=ss[0]*(1.f/(float)HWs); mxo[bc]=sm[0]; }
}
__global__ void cagate_k(const float* __restrict__ amean, const float* __restrict__ amax,
    const float* __restrict__ aw1, const float* __restrict__ ab1,
    const float* __restrict__ aw2, const float* __restrict__ ab2,
    const float* __restrict__ mw1, const float* __restrict__ mb1,
    const float* __restrict__ mw2, const float* __restrict__ mb2, float* __restrict__ gate){
    __shared__ float ha[16], hm[16];
    int b=blockIdx.x, t=threadIdx.x;
    if (t<16){ float s=ab1[t]; for (int i=0;i<CC;i++) s+=aw1[t*CC+i]*amean[b*CC+i]; ha[t]=fmaxf(s,0.f); }
    else if (t<32){ int u=t-16; float s=mb1[u]; for (int i=0;i<CC;i++) s+=mw1[u*CC+i]*amax[b*CC+i]; hm[u]=fmaxf(s,0.f); }
    __syncthreads();
    float g = ab2[t]+mb2[t];
    #pragma unroll
    for (int k=0;k<16;k++) g += aw2[t*16+k]*ha[k] + mw2[t*16+k]*hm[k];
    gate[b*CC+t] = sigmoidf_(g);
}
__global__ void cvtw_k(const float* __restrict__ W, int RS, int K, const float* __restrict__ gate,
                       __half* __restrict__ oh){
    int idx = blockIdx.x*256 + threadIdx.x;
    int b = idx/(256*K); int rem = idx - b*256*K; int m = rem/K, k = rem - m*K;
    float v = W[(long)m*RS + k];
    if (gate) v *= gate[b*256 + k];
    oh[idx] = __float2half_rn(v);
}
__global__ void bcat_k(const float* __restrict__ b1, const float* __restrict__ b2,
                       const float* __restrict__ b3, float* __restrict__ o){
    int t = blockIdx.x*256 + threadIdx.x;
    if (t<256) o[t]=b1[t];
    else if (t<512) o[t]=b2[t-256];
    else if (t<768) o[t]=b2[t-512];
    else if (t<1024) o[t]=b1[t-768];
    else if (t<1280) o[t]=b3[t-1024];
}

// ---- HMMA GEMM 1-pass, 4-stage cp.async, batch+group dims: by = g*8 + b ----
#define STG 29184u
#define GSM (4*29184)
__global__ void __launch_bounds__(256,1) gemm_mma(
    const __half* __restrict__ Wh, long wBS, long wGS, int K,
    const __half* __restrict__ X0h, const __half* __restrict__ X1h, long xGS,
    float* __restrict__ Yf, __half* __restrict__ Yh, __half* __restrict__ Yl, long yGS,
    const float* __restrict__ bias, int biasGS, int epi,
    const void* __restrict__ E0, long e0GS, const float* __restrict__ E1)
{
    extern __shared__ __align__(16) char smem[];
    u32 sm = smem_u32(smem);
    int tid=threadIdx.x, lane=tid&31, wid=tid>>5;
    int n0 = blockIdx.x*128;
    int by = blockIdx.y, b = by & 7, g = by >> 3;
    int wm = (wid&1)*128, wn = (wid>>1)*32;
    int lr = lane&15, lc8 = (lane>>4)*8;
    const __half* WhB = Wh + (long)b*wBS + (long)g*wGS;
    const __half* X0 = X0h + (long)g*xGS;
    const float* biasg = bias + g*biasGS;
    int NC = K>>5;
    float acc[32][4];
    #pragma unroll
    for (int i=0;i<32;i++){ acc[i][0]=0;acc[i][1]=0;acc[i][2]=0;acc[i][3]=0; }
    for (int c=0; c<NC+3; c++){
        __syncthreads();
        if (c<NC){
            u32 st = sm + (u32)(c&3)*STG;
            int kb = c*32;
            #pragma unroll
            for (int j=0;j<4;j++){
                int o=tid+256*j, r=o>>2, cb=o&3;
                cpa(st + (u32)(r*80+cb*16), WhB + (size_t)r*K + kb + cb*8);
            }
            const __half *xh=X0; int kk=kb;
            if (kk>=256){ xh=X1h; kk-=256; }
            #pragma unroll
            for (int j=0;j<2;j++){
                int o=tid+256*j, r=o>>4, cb=o&15;
                size_t s = ((size_t)b*256 + kk + r)*HWs + n0 + cb*8;
                cpa(st + 20480u + (u32)(r*272+cb*16), xh + s);
            }
            cpcommit();
        }
        if (c<3) continue;
        int cc = c-3;
        int iw = ((c<NC-1)?c:(NC-1)) - cc;
        cpwait(iw);
        __syncthreads();
        u32 sA = sm + (u32)(cc&3)*STG;
        #pragma unroll
        for (int ks=0; ks<32; ks+=16){
            u32 bh[4][2];
            #pragma unroll
            for (int pr=0; pr<2; pr++){
                u32 off = (u32)((ks+lr)*272 + (wn+pr*16+lc8)*2);
                ldsm4t(bh[pr*2][0],bh[pr*2][1],bh[pr*2+1][0],bh[pr*2+1][1], sA+20480u+off);
            }
            #pragma unroll
            for (int mt=0; mt<8; mt++){
                u32 ah[4];
                u32 off = (u32)((wm+mt*16+lr)*80 + (ks+lc8)*2);
                ldsm4(ah[0],ah[1],ah[2],ah[3], sA+off);
                #pragma unroll
                for (int nt=0; nt<4; nt++)
                    mmah(acc[mt*4+nt], ah, bh[nt]);
            }
        }
    }
    __half* Yhg = Yh ? Yh + (long)g*yGS : 0;
    __half* Ylg = Yl ? Yl + (long)g*yGS : 0;
    #pragma unroll
    for (int mt=0; mt<8; mt++){
        #pragma unroll
        for (int nt=0; nt<4; nt++){
            float* cc = acc[mt*4+nt];
            int n = n0 + wn + nt*8 + (lane&3)*2;
            #pragma unroll
            for (int hlf=0; hlf<2; hlf++){
                int m = wm + mt*16 + (lane>>2) + hlf*8;
                float v0 = cc[hlf*2] + biasg[m], v1 = cc[hlf*2+1] + biasg[m];
                long yb = ((long)b*CC + m)*HWs + n;
                if (epi==1){ v0=fmaxf(v0,0.f); v1=fmaxf(v1,0.f); }
                else if (epi==2){
                    const __half* eh = (const __half*)E0 + (long)g*e0GS + yb;
                    u32 pv = *(const u32*)eh; __half2 h2v = *(__half2*)&pv;
                    v0 += __half2float(h2v.x); v1 += __half2float(h2v.y);
                }
                else if (epi==3){ const float* ef=(const float*)E0;
                    v0=sigmoidf_(v0)*ef[yb]; v1=sigmoidf_(v1)*ef[yb+1]; }
                else if (epi==4){ float wl=E1[(long)m*513+512]; long eb=(long)b*HWs+n;
                    const float* ef=(const float*)E0;
                    v0+=wl*ef[eb]; v1+=wl*ef[eb+1]; }
                if (Yf){ float2 st={v0,v1}; *(float2*)(Yf+yb)=st; }
                else   w2(Yhg, Ylg, yb, v0, v1);
            }
        }
    }
}

// ---- HMMA score (A=Q 2-pass, B=S hi), 3-stage; softmax over j ----
#define SSTG 26112u
#define SSM (3*26112)
template<int WRITE_M>
__global__ void __launch_bounds__(256,1) score_mma(
    const __half* __restrict__ Qh, const __half* __restrict__ Ql,
    const __half* __restrict__ Sh,
    __half* __restrict__ Mh, float* __restrict__ mOut)
{
    extern __shared__ __align__(16) char smem[];
    u32 sm = smem_u32(smem);
    float* smE = (float*)smem;
    int tid=threadIdx.x, lane=tid&31, wid=tid>>5;
    int h = blockIdx.x, b = blockIdx.y;
    int wm=(wid&1)*64, wn=(wid>>1)*32;
    int lr=lane&15, lc8=(lane>>4)*8;
    float acc[16][4];
    #pragma unroll
    for (int i=0;i<16;i++){ acc[i][0]=0;acc[i][1]=0;acc[i][2]=0;acc[i][3]=0; }
    for (int c=0;c<10;c++){
        __syncthreads();
        if (c<8){
            u32 st = sm + (u32)(c%3)*SSTG;
            int kb = c*32;
            #pragma unroll
            for (int j=0;j<2;j++){
                int o = tid + 256*j, r = o>>4, cb = o&15;
                size_t s = ((size_t)(b*256 + kb + r))*HWs + h*128 + cb*8;
                u32 d = st + (u32)(r*272 + cb*16);
                cpa(d, Qh+s); cpa(d+8704u, Ql+s); cpa(d+17408u, Sh+s);
            }
            cpcommit();
        }
        if (c<2) continue;
        int cc = c-2;
        int iw = ((c<7)?c:7) - cc;
        cpwait(iw);
        __syncthreads();
        u32 sA = sm + (u32)(cc%3)*SSTG;
        #pragma unroll
        for (int ks=0;ks<32;ks+=16){
            u32 bh[4][2];
            #pragma unroll
            for (int pr=0;pr<2;pr++){
                u32 off = (u32)((ks+lr)*272 + (wn+pr*16+lc8)*2);
                ldsm4t(bh[pr*2][0],bh[pr*2][1],bh[pr*2+1][0],bh[pr*2+1][1], sA+17408u+off);
            }
            #pragma unroll
            for (int mt=0;mt<4;mt++){
                u32 r0,r1,r2,r3,q0,q1,q2,q3;
                u32 off = (u32)((ks+lr)*272 + (wm+mt*16+lc8)*2);
                ldsm4t(r0,r1,r2,r3, sA+off);
                ldsm4t(q0,q1,q2,q3, sA+8704u+off);
                u32 ah[4]={r0,r2,r1,r3}, al[4]={q0,q2,q1,q3};
                #pragma unroll
                for (int nt=0;nt<4;nt++){
                    float* cc2 = acc[mt*4+nt];
                    mmah(cc2, ah, bh[nt]); mmah(cc2, al, bh[nt]);
                }
            }
        }
    }
    __syncthreads();
    #pragma unroll
    for (int mt=0;mt<4;mt++)
        #pragma unroll
        for (int nt=0;nt<4;nt++){
            float* cc = acc[mt*4+nt];
            int n = wn + nt*8 + (lane&3)*2;
            #pragma unroll
            for (int hlf=0;hlf<2;hlf++){
                int m = wm + mt*16 + (lane>>2) + hlf*8;
                smE[m*132+n] = cc[hlf*2]; smE[m*132+n+1] = cc[hlf*2+1];
            }
        }
    __syncthreads();
    int row = tid>>1, c0 = (tid&1)*64;
    float* rp = smE + row*132 + c0;
    float mx = -INFINITY;
    for (int j=0;j<64;j++) mx = fmaxf(mx, rp[j]);
    mx = fmaxf(mx, __shfl_xor_sync(0xffffffffu, mx, 1));
    float sum = 0.f;
    for (int j=0;j<64;j++){ float e = expf(rp[j]-mx); rp[j] = e; sum += e; }
    sum += __shfl_xor_sync(0xffffffffu, sum, 1);
    float inv = 1.f/sum;
    if (WRITE_M){
        long base = ((long)(b*128+h)*128 + row)*128 + c0;
        for (int j=0;j<64;j+=2)
            ((u32*)Mh)[(base+j)>>1] = pack2(rp[j]*inv, rp[j+1]*inv);
    } else {
        for (int j=0;j<64;j++) rp[j] *= inv;
        __syncthreads();
        if (tid < 128){
            float t = 0.f;
            for (int i=0;i<128;i++) t += smE[i*132+tid];
            mOut[(long)b*HWs + h*128 + tid] = (t>0.1f)?0.f:1.f;
        }
    }
}

// ---- HMMA attend (1-pass) ----
__global__ void __launch_bounds__(256,1) attend_mma(
    const __half* __restrict__ Mh,
    const __half* __restrict__ Vh,
    __half* __restrict__ Oh)
{
    extern __shared__ __align__(16) char smem[];
    u32 sm = smem_u32(smem);
    int tid=threadIdx.x, lane=tid&31, wid=tid>>5;
    int c0 = blockIdx.x*128, bh = blockIdx.y, b = bh>>7, h = bh&127;
    int wm=(wid&1)*64, wn=(wid>>1)*32;
    int lr=lane&15, lc8=(lane>>4)*8;
    int tile=lane>>3, lrow=lane&7;
    float acc[16][4];
    #pragma unroll
    for (int i=0;i<16;i++){ acc[i][0]=0;acc[i][1]=0;acc[i][2]=0;acc[i][3]=0; }
    for (int c=0;c<=4;c++){
        if (c<4){
            u32 st = sm + (u32)(c&1)*20480u;
            int kb = c*32;
            #pragma unroll
            for (int j=0;j<2;j++){
                int o = tid + 256*j, r = o>>2, cb = o&3;
                u32 d = st + (u32)(r*80 + cb*16);
                size_t s = ((size_t)(b*256 + c0 + r))*HWs + h*128 + kb + cb*8;
                cpa(d, Vh+s);
                size_t s2 = (((size_t)(b*128+h)*128 + r))*128 + kb + cb*8;
                cpa(d+10240u, Mh+s2);
            }
            cpcommit();
        }
        if (c==0) continue;
        cpwait((c<4)?1:0);
        __syncthreads();
        u32 sA = sm + (u32)((c-1)&1)*20480u;
        #pragma unroll
        for (int ks=0;ks<32;ks+=16){
            u32 bh_[4][2];
            #pragma unroll
            for (int pr=0;pr<2;pr++){
                u32 off = (u32)(((wn+pr*16+(tile>>1)*8+lrow)*40 + ks + (tile&1)*8)*2);
                u32 r0,r1,r2,r3;
                ldsm4(r0,r1,r2,r3, sA+10240u+off);
                bh_[pr*2][0]=r0; bh_[pr*2][1]=r1; bh_[pr*2+1][0]=r2; bh_[pr*2+1][1]=r3;
            }
            #pragma unroll
            for (int mt=0;mt<4;mt++){
                u32 ah[4];
                u32 off = (u32)((wm+mt*16+lr)*80 + (ks+lc8)*2);
                ldsm4(ah[0],ah[1],ah[2],ah[3], sA+off);
                #pragma unroll
                for (int nt=0;nt<4;nt++)
                    mmah(acc[mt*4+nt], ah, bh_[nt]);
            }
        }
        __syncthreads();
    }
    #pragma unroll
    for (int mt=0;mt<4;mt++)
        #pragma unroll
        for (int nt=0;nt<4;nt++){
            float* cc = acc[mt*4+nt];
            int n = wn + nt*8 + (lane&3)*2;
            #pragma unroll
            for (int hlf=0;hlf<2;hlf++){
                int m = wm + mt*16 + (lane>>2) + hlf*8;
                long idx = ((long)(b*256 + c0 + m))*HWs + h*128 + n;
                ((u32*)Oh)[idx>>1] = pack2(cc[hlf*2], cc[hlf*2+1]);
            }
        }
}

// ---- fused morphology ----
__device__ void morp(float* dst, const float* src, int r, int erode, int D, int t, int NT){
    int r2 = r*r;
    for (int i=t; i<D*D; i+=NT){
        int h = i/D, w = i - h*D;
        float res = erode ? 1.f : 0.f;
        for (int dy=-r; dy<=r; dy++) for (int dx=-r; dx<=r; dx++){
            if (dy*dy+dx*dx > r2) continue;
            int hh=h+dy, ww=w+dx;
            float v = (hh>=0&&hh<D&&ww>=0&&ww<D) ? src[hh*MS+ww] : 0.f;
            if (erode){ if (v<0.5f) res=0.f; } else if (v>0.5f) res=1.f;
        }
        dst[h*MS+w] = res;
    }
}
__global__ void morphall_k(const float* __restrict__ src, float* __restrict__ dst){
    extern __shared__ float sA[];
    float* A = sA; float* B = sA + MS*MS;
    int b = blockIdx.x, t = threadIdx.x, NT = blockDim.x;
    for (int i=t;i<MS*MS;i+=NT){ A[i]=0.f; B[i]=0.f; }
    __syncthreads();
    for (int i=t;i<HWs;i+=NT){ int h=i>>7, w=i&127; A[h*MS+w]=src[(long)b*HWs+i]; }
    __syncthreads();
    morp(B,A,2,1,128,t,NT); __syncthreads();
    morp(A,B,2,0,128,t,NT); __syncthreads();
    morp(B,A,1,0,128,t,NT); __syncthreads();
    morp(A,B,1,1,128,t,NT); __syncthreads();
    for (int i=t;i<MS*MS;i+=NT){
        int h=i/MS, w=i-h*MS;
        float v = 0.f;
        if (h>=3 && h<131 && w>=3 && w<131) v = A[(h-3)*MS + (w-3)];
        B[i] = v;
    }
    __syncthreads();
    morp(A,B,3,0,MS,t,NT); __syncthreads();
    morp(B,A,3,1,MS,t,NT); __syncthreads();
    for (int i=t;i<HWs;i+=NT){ int h=i>>7, w=i&127; dst[(long)b*HWs+i] = 1.f - B[(h+3)*MS + (w+3)]; }
}

extern "C" void kernel_launch(void* const* d_in, const int* in_sizes, int n_in,
                              void* d_out, int out_size) {
    const float* x_p=(const float*)d_in[0];  const float* x_c=(const float*)d_in[1];
    const float* pa_w1=(const float*)d_in[2];const float* pa_b1=(const float*)d_in[3];
    const float* pa_w2=(const float*)d_in[4];const float* pa_b2=(const float*)d_in[5];
    const float* pa_wc=(const float*)d_in[6];const float* pa_bc=(const float*)d_in[7];
    const float* ca_aw1=(const float*)d_in[8];const float* ca_ab1=(const float*)d_in[9];
    const float* ca_aw2=(const float*)d_in[10];const float* ca_ab2=(const float*)d_in[11];
    const float* ca_mw1=(const float*)d_in[12];const float* ca_mb1=(const float*)d_in[13];
    const float* ca_mw2=(const float*)d_in[14];const float* ca_mb2=(const float*)d_in[15];
    const float* b1_w=(const float*)d_in[16];const float* b1_b=(const float*)d_in[17];
    const float* b2_w=(const float*)d_in[18];const float* b2_b=(const float*)d_in[19];
    const float* b3_w=(const float*)d_in[20];const float* b3_b=(const float*)d_in[21];
    const float* fus_w=(const float*)d_in[22];const float* fus_b=(const float*)d_in[23];
    float* out=(float*)d_out;

    float *gate,*amean,*amax,*mA,*vfin,*bcat;
    __half *ih,*il,*wh,*Mh;
    cudaGetSymbolAddress((void**)&gate,g_gate);
    cudaGetSymbolAddress((void**)&amean,g_amean); cudaGetSymbolAddress((void**)&amax,g_amax);
    cudaGetSymbolAddress((void**)&mA,g_mA);
    cudaGetSymbolAddress((void**)&vfin,g_vfinal);
    cudaGetSymbolAddress((void**)&bcat,g_bcat);
    cudaGetSymbolAddress((void**)&ih,g_imgh); cudaGetSymbolAddress((void**)&il,g_imgl);
    cudaGetSymbolAddress((void**)&wh,g_wih);
    cudaGetSymbolAddress((void**)&Mh,g_Mh);
    cudaFuncSetAttribute(gemm_mma, cudaFuncAttributeMaxDynamicSharedMemorySize, GSM);
    cudaFuncSetAttribute(score_mma<1>, cudaFuncAttributeMaxDynamicSharedMemorySize, SSM);
    cudaFuncSetAttribute(score_mma<0>, cudaFuncAttributeMaxDynamicSharedMemorySize, SSM);
    cudaFuncSetAttribute(attend_mma, cudaFuncAttributeMaxDynamicSharedMemorySize, 40960);
    cudaFuncSetAttribute(morphall_k, cudaFuncAttributeMaxDynamicSharedMemorySize, 2*MS*MS*4);

    const long W1=0, W2=65536, WC=131072, B1=262144, B2=327680, FU=393216;
    const long B2G=524288, B1G=1048576, B3R=1572864;
    dim3 g2(128,16), g1(128,8), g3(128,24);
    dim3 gs(HH, BB), ga(2, BB*HH);

    pool_k<<<NBCHW/256,256>>>(x_p, ih+IK(3), ih+IK(4), ih+IK(0));
    reduce_k<<<BB*CC,256>>>(x_c, amean, amax, ih+IK(1));
    cagate_k<<<BB,256>>>(amean,amax,ca_aw1,ca_ab1,ca_aw2,ca_ab2,ca_mw1,ca_mb1,ca_mw2,ca_mb2,gate);
    cvtw_k<<<256,256>>>(pa_w1,256,256,0, wh+W1);
    bcat_k<<<5,256>>>(b1_b, b2_b, b3_b, bcat);
    // merged h1+h2 (relu) -> I5,I6
    gemm_mma<<<g2,256,GSM>>>(wh+W1,0,0,256, ih+IK(3),0,IK(1), 0,ih+IK(5),0,IK(1),
                             pa_b1,0,1, 0,0,0);
    cvtw_k<<<256,256>>>(pa_w2,256,256,0, wh+W2);
    gemm_mma<<<g2,256,GSM>>>(wh+W2,0,0,256, ih+IK(5),0,IK(1), 0,ih+IK(7),0,IK(1),
                             pa_b2,0,2, ih+IK(3),IK(1),0);
    cvtw_k<<<512,256>>>(pa_wc,512,512,0, wh+WC);
    gemm_mma<<<g1,256,GSM>>>(wh+WC,0,0,512, ih+IK(7),ih+IK(8),0, 0,ih+IK(2),0,0,
                             pa_bc,0,3, x_p,0,0);
    cvtw_k<<<256,256>>>(b1_w,256,256,0, wh+B1);
    cvtw_k<<<256,256>>>(b2_w,256,256,0, wh+B2);
    // merged Q1+S2 -> I3,I4 (hi+lo)
    gemm_mma<<<g2,256,GSM>>>(wh+B1,0,65536,256, ih+IK(2),0,0, 0,ih+IK(3),il+IK(3),IK(1),
                             bcat,256,0, 0,0,0);
    cvtw_k<<<2048,256>>>(b2_w,256,256,gate, wh+B2G);
    cvtw_k<<<2048,256>>>(b1_w,256,256,gate, wh+B1G);
    cvtw_k<<<2048,256>>>(b3_w,256,256,0, wh+B3R);
    // merged S1+Q2+v3 -> I5,I6,I7 (hi+lo)
    gemm_mma<<<g3,256,GSM>>>(wh+B2G,65536,524288,256, ih+IK(1),0,0, 0,ih+IK(5),il+IK(5),IK(1),
                             bcat+512,256,0, 0,0,0);
    // scores
    score_mma<1><<<gs,256,SSM>>>(ih+IK(3),il+IK(3), ih+IK(5), Mh, 0);
    score_mma<0><<<gs,256,SSM>>>(ih+IK(6),il+IK(6), ih+IK(4), 0, mA);
    // morphology
    morphall_k<<<BB,1024,2*MS*MS*4>>>(mA, vfin);
    // attend -> I8
    attend_mma<<<ga,256,40960>>>(Mh, ih+IK(7), ih+IK(8));
    // fusion
    cvtw_k<<<512,256>>>(fus_w,513,512,0, wh+FU);
    gemm_mma<<<g1,256,GSM>>>(wh+FU,0,0,512, ih+IK(8),ih+IK(0),0, out,0,0,0,
                             fus_b,0,4, vfin,0,fus_w);
}

// round 16
// speedup vs baseline: 1.3268x; 1.0414x over previous
#include <cuda_runtime.h>
#include <cuda_fp16.h>
#include <math.h>

#define BB 8
#define CC 256
#define HH 128
#define WW 128
#define HWs 16384
#define NBCHW (BB*CC*HWs)
#define MS 134
typedef unsigned long long ull;
typedef unsigned int u32;

__device__ float g_mA[BB*HWs];
__device__ float g_vfinal[BB*HWs];
__device__ float g_gate[BB*CC];
__device__ float g_amean[BB*CC];
__device__ float g_amax[BB*CC];
__device__ float g_bcat[1280];
__device__ __align__(16) __half g_imgh[335544320];
__device__ __align__(16) __half g_imgl[335544320];
__device__ __align__(16) __half g_Mh[16777216];
__device__ __align__(16) __half g_wih[2097152];
#define IK(k) ((long)(k)*33554432L)

__device__ __forceinline__ float sigmoidf_(float x){ return 1.0f/(1.0f+expf(-x)); }
__device__ __forceinline__ u32 smem_u32(const void* p){
    u32 a; asm("{ .reg .u64 t; cvta.to.shared.u64 t, %1; cvt.u32.u64 %0, t; }" : "=r"(a) : "l"(p)); return a; }
__device__ __forceinline__ u32 pack2(float a, float b){
    __half2 t = __floats2half2_rn(a, b); return *(u32*)&t; }
__device__ __forceinline__ void w2(__half* oh, __half* ol, long idx, float a, float b){
    u32 h = pack2(a,b); __half2 hv = *(__half2*)&h;
    ((u32*)oh)[idx>>1] = h;
    if (ol) ((u32*)ol)[idx>>1] = pack2(a-__half2float(hv.x), b-__half2float(hv.y));
}
__device__ __forceinline__ void ldsm4(u32& r0,u32& r1,u32& r2,u32& r3,u32 a){
    asm volatile("ldmatrix.sync.aligned.m8n8.x4.shared.b16 {%0,%1,%2,%3}, [%4];"
        :"=r"(r0),"=r"(r1),"=r"(r2),"=r"(r3):"r"(a)); }
__device__ __forceinline__ void ldsm4t(u32& r0,u32& r1,u32& r2,u32& r3,u32 a){
    asm volatile("ldmatrix.sync.aligned.m8n8.x4.trans.shared.b16 {%0,%1,%2,%3}, [%4];"
        :"=r"(r0),"=r"(r1),"=r"(r2),"=r"(r3):"r"(a)); }
__device__ __forceinline__ void mmah(float* c, const u32* a, const u32* b){
    asm volatile("mma.sync.aligned.m16n8k16.row.col.f32.f16.f16.f32 "
        "{%0,%1,%2,%3},{%4,%5,%6,%7},{%8,%9},{%0,%1,%2,%3};"
        :"+f"(c[0]),"+f"(c[1]),"+f"(c[2]),"+f"(c[3])
        :"r"(a[0]),"r"(a[1]),"r"(a[2]),"r"(a[3]),"r"(b[0]),"r"(b[1])); }
__device__ __forceinline__ void cpa(u32 d, const void* s){
    asm volatile("cp.async.cg.shared.global [%0], [%1], 16;"::"r"(d),"l"(s)); }
__device__ __forceinline__ void cpcommit(){ asm volatile("cp.async.commit_group;":::"memory"); }
__device__ __forceinline__ void cpwait(int n){
    if (n>=3) asm volatile("cp.async.wait_group 3;":::"memory");
    else if (n==2) asm volatile("cp.async.wait_group 2;":::"memory");
    else if (n==1) asm volatile("cp.async.wait_group 1;":::"memory");
    else asm volatile("cp.async.wait_group 0;":::"memory");
}

// ---- pool: y1h,y2h + x_p image ----
__global__ void pool_k(const float* __restrict__ xp, __half* __restrict__ y1h,
                       __half* __restrict__ y2h, __half* __restrict__ xph){
    long idx = (long)blockIdx.x*256 + threadIdx.x;
    if (idx >= (long)NBCHW) return;
    int w = (int)(idx & 127), h = (int)((idx>>7)&127);
    long base = idx - (long)(h*WW+w);
    float s=0.f, mx=-INFINITY, ctr=0.f;
    #pragma unroll
    for (int dy=-1;dy<=1;dy++){ int hh=h+dy; if(hh<0||hh>=HH) continue;
        #pragma unroll
        for (int dx=-1;dx<=1;dx++){ int ww=w+dx; if(ww<0||ww>=WW) continue;
            float v = xp[base+hh*WW+ww]; s+=v; mx=fmaxf(mx,v);
            if (dy==0&&dx==0) ctr=v; } }
    y1h[idx]=__float2half_rn(s*(1.f/9.f)); y2h[idx]=__float2half_rn(mx);
    xph[idx]=__float2half_rn(ctr);
}
// ---- reduce + x_c image ----
__global__ void reduce_k(const float* __restrict__ x, float* __restrict__ mean,
                         float* __restrict__ mxo, __half* __restrict__ xch){
    __shared__ float ss[256], sm[256];
    int bc=blockIdx.x, t=threadIdx.x;
    const float* p = x + (long)bc*HWs;
    __half* q = xch + (long)bc*HWs;
    float s=0.f, m=-INFINITY;
    for (int i=t;i<HWs;i+=256){ float v=p[i]; s+=v; m=fmaxf(m,v); q[i]=__float2half_rn(v); }
    ss[t]=s; sm[t]=m; __syncthreads();
    for (int o=128;o>0;o>>=1){ if (t<o){ ss[t]+=ss[t+o]; sm[t]=fmaxf(sm[t],sm[t+o]); } __syncthreads(); }
    if (t==0){ mean[bc]=ss[0]*(1.f/(float)HWs); mxo[bc]=sm[0]; }
}
__global__ void cagate_k(const float* __restrict__ amean, const float* __restrict__ amax,
    const float* __restrict__ aw1, const float* __restrict__ ab1,
    const float* __restrict__ aw2, const float* __restrict__ ab2,
    const float* __restrict__ mw1, const float* __restrict__ mb1,
    const float* __restrict__ mw2, const float* __restrict__ mb2, float* __restrict__ gate){
    __shared__ float ha[16], hm[16];
    int b=blockIdx.x, t=threadIdx.x;
    if (t<16){ float s=ab1[t]; for (int i=0;i<CC;i++) s+=aw1[t*CC+i]*amean[b*CC+i]; ha[t]=fmaxf(s,0.f); }
    else if (t<32){ int u=t-16; float s=mb1[u]; for (int i=0;i<CC;i++) s+=mw1[u*CC+i]*amax[b*CC+i]; hm[u]=fmaxf(s,0.f); }
    __syncthreads();
    float g = ab2[t]+mb2[t];
    #pragma unroll
    for (int k=0;k<16;k++) g += aw2[t*16+k]*ha[k] + mw2[t*16+k]*hm[k];
    gate[b*CC+t] = sigmoidf_(g);
}
__global__ void cvtw_k(const float* __restrict__ W, int RS, int K, const float* __restrict__ gate,
                       __half* __restrict__ oh){
    int idx = blockIdx.x*256 + threadIdx.x;
    int b = idx/(256*K); int rem = idx - b*256*K; int m = rem/K, k = rem - m*K;
    float v = W[(long)m*RS + k];
    if (gate) v *= gate[b*256 + k];
    oh[idx] = __float2half_rn(v);
}
__global__ void bcat_k(const float* __restrict__ b1, const float* __restrict__ b2,
                       const float* __restrict__ b3, float* __restrict__ o){
    int t = blockIdx.x*256 + threadIdx.x;
    if (t<256) o[t]=b1[t];
    else if (t<512) o[t]=b2[t-256];
    else if (t<768) o[t]=b2[t-512];
    else if (t<1024) o[t]=b1[t-768];
    else if (t<1280) o[t]=b3[t-1024];
}

// ---- HMMA GEMM 1-pass, 4-stage cp.async, batch+group dims: by = g*8 + b ----
#define STG 29184u
#define GSM (4*29184)
__global__ void __launch_bounds__(256,1) gemm_mma(
    const __half* __restrict__ Wh, long wBS, long wGS, int K,
    const __half* __restrict__ X0h, const __half* __restrict__ X1h, long xGS,
    float* __restrict__ Yf, __half* __restrict__ Yh, __half* __restrict__ Yl, long yGS,
    const float* __restrict__ bias, int biasGS, int epi,
    const void* __restrict__ E0, long e0GS, const float* __restrict__ E1)
{
    extern __shared__ __align__(16) char smem[];
    u32 sm = smem_u32(smem);
    int tid=threadIdx.x, lane=tid&31, wid=tid>>5;
    int n0 = blockIdx.x*128;
    int by = blockIdx.y, b = by & 7, g = by >> 3;
    int wm = (wid&1)*128, wn = (wid>>1)*32;
    int lr = lane&15, lc8 = (lane>>4)*8;
    const __half* WhB = Wh + (long)b*wBS + (long)g*wGS;
    const __half* X0 = X0h + (long)g*xGS;
    const float* biasg = bias + g*biasGS;
    int NC = K>>5;
    float acc[32][4];
    #pragma unroll
    for (int i=0;i<32;i++){ acc[i][0]=0;acc[i][1]=0;acc[i][2]=0;acc[i][3]=0; }
    for (int c=0; c<NC+3; c++){
        __syncthreads();
        if (c<NC){
            u32 st = sm + (u32)(c&3)*STG;
            int kb = c*32;
            #pragma unroll
            for (int j=0;j<4;j++){
                int o=tid+256*j, r=o>>2, cb=o&3;
                cpa(st + (u32)(r*80+cb*16), WhB + (size_t)r*K + kb + cb*8);
            }
            const __half *xh=X0; int kk=kb;
            if (kk>=256){ xh=X1h; kk-=256; }
            #pragma unroll
            for (int j=0;j<2;j++){
                int o=tid+256*j, r=o>>4, cb=o&15;
                size_t s = ((size_t)b*256 + kk + r)*HWs + n0 + cb*8;
                cpa(st + 20480u + (u32)(r*272+cb*16), xh + s);
            }
            cpcommit();
        }
        if (c<3) continue;
        int cc = c-3;
        int iw = ((c<NC-1)?c:(NC-1)) - cc;
        cpwait(iw);
        __syncthreads();
        u32 sA = sm + (u32)(cc&3)*STG;
        #pragma unroll
        for (int ks=0; ks<32; ks+=16){
            u32 bh[4][2];
            #pragma unroll
            for (int pr=0; pr<2; pr++){
                u32 off = (u32)((ks+lr)*272 + (wn+pr*16+lc8)*2);
                ldsm4t(bh[pr*2][0],bh[pr*2][1],bh[pr*2+1][0],bh[pr*2+1][1], sA+20480u+off);
            }
            #pragma unroll
            for (int mt=0; mt<8; mt++){
                u32 ah[4];
                u32 off = (u32)((wm+mt*16+lr)*80 + (ks+lc8)*2);
                ldsm4(ah[0],ah[1],ah[2],ah[3], sA+off);
                #pragma unroll
                for (int nt=0; nt<4; nt++)
                    mmah(acc[mt*4+nt], ah, bh[nt]);
            }
        }
    }
    __half* Yhg = Yh ? Yh + (long)g*yGS : 0;
    __half* Ylg = Yl ? Yl + (long)g*yGS : 0;
    #pragma unroll
    for (int mt=0; mt<8; mt++){
        #pragma unroll
        for (int nt=0; nt<4; nt++){
            float* cc = acc[mt*4+nt];
            int n = n0 + wn + nt*8 + (lane&3)*2;
            #pragma unroll
            for (int hlf=0; hlf<2; hlf++){
                int m = wm + mt*16 + (lane>>2) + hlf*8;
                float v0 = cc[hlf*2] + biasg[m], v1 = cc[hlf*2+1] + biasg[m];
                long yb = ((long)b*CC + m)*HWs + n;
                if (epi==1){ v0=fmaxf(v0,0.f); v1=fmaxf(v1,0.f); }
                else if (epi==2){
                    const __half* eh = (const __half*)E0 + (long)g*e0GS + yb;
                    u32 pv = *(const u32*)eh; __half2 h2v = *(__half2*)&pv;
                    v0 += __half2float(h2v.x); v1 += __half2float(h2v.y);
                }
                else if (epi==3){ const float* ef=(const float*)E0;
                    v0=sigmoidf_(v0)*ef[yb]; v1=sigmoidf_(v1)*ef[yb+1]; }
                else if (epi==4){ float wl=E1[(long)m*513+512]; long eb=(long)b*HWs+n;
                    const float* ef=(const float*)E0;
                    v0+=wl*ef[eb]; v1+=wl*ef[eb+1]; }
                if (Yf){ float2 st={v0,v1}; *(float2*)(Yf+yb)=st; }
                else   w2(Yhg, Ylg, yb, v0, v1);
            }
        }
    }
}

// ---- merged HMMA score: by = variant*8 + b. variant 0: 2-pass Q, write M.
//      variant 1: 1-pass Q, colsum -> mask. 3-stage. ----
#define SSTG 26112u
#define SSM (3*26112)
__global__ void __launch_bounds__(256,1) score_mma(
    const __half* __restrict__ Q0h, const __half* __restrict__ Q0l, const __half* __restrict__ S0h,
    const __half* __restrict__ Q1h, const __half* __restrict__ S1h,
    __half* __restrict__ Mh, float* __restrict__ mOut)
{
    extern __shared__ __align__(16) char smem[];
    u32 sm = smem_u32(smem);
    float* smE = (float*)smem;
    int tid=threadIdx.x, lane=tid&31, wid=tid>>5;
    int h = blockIdx.x, by = blockIdx.y, b = by & 7, var = by >> 3;
    const __half* Qh = var ? Q1h : Q0h;
    const __half* Sh = var ? S1h : S0h;
    int wm=(wid&1)*64, wn=(wid>>1)*32;
    int lr=lane&15, lc8=(lane>>4)*8;
    float acc[16][4];
    #pragma unroll
    for (int i=0;i<16;i++){ acc[i][0]=0;acc[i][1]=0;acc[i][2]=0;acc[i][3]=0; }
    for (int c=0;c<10;c++){
        __syncthreads();
        if (c<8){
            u32 st = sm + (u32)(c%3)*SSTG;
            int kb = c*32;
            #pragma unroll
            for (int j=0;j<2;j++){
                int o = tid + 256*j, r = o>>4, cb = o&15;
                size_t s = ((size_t)(b*256 + kb + r))*HWs + h*128 + cb*8;
                u32 d = st + (u32)(r*272 + cb*16);
                cpa(d, Qh+s); cpa(d+17408u, Sh+s);
                if (!var) cpa(d+8704u, Q0l+s);
            }
            cpcommit();
        }
        if (c<2) continue;
        int cc = c-2;
        int iw = ((c<7)?c:7) - cc;
        cpwait(iw);
        __syncthreads();
        u32 sA = sm + (u32)(cc%3)*SSTG;
        #pragma unroll
        for (int ks=0;ks<32;ks+=16){
            u32 bh[4][2];
            #pragma unroll
            for (int pr=0;pr<2;pr++){
                u32 off = (u32)((ks+lr)*272 + (wn+pr*16+lc8)*2);
                ldsm4t(bh[pr*2][0],bh[pr*2][1],bh[pr*2+1][0],bh[pr*2+1][1], sA+17408u+off);
            }
            #pragma unroll
            for (int mt=0;mt<4;mt++){
                u32 r0,r1,r2,r3;
                u32 off = (u32)((ks+lr)*272 + (wm+mt*16+lc8)*2);
                ldsm4t(r0,r1,r2,r3, sA+off);
                u32 ah[4]={r0,r2,r1,r3};
                #pragma unroll
                for (int nt=0;nt<4;nt++) mmah(acc[mt*4+nt], ah, bh[nt]);
                if (!var){
                    u32 q0,q1,q2,q3;
                    ldsm4t(q0,q1,q2,q3, sA+8704u+off);
                    u32 al[4]={q0,q2,q1,q3};
                    #pragma unroll
                    for (int nt=0;nt<4;nt++) mmah(acc[mt*4+nt], al, bh[nt]);
                }
            }
        }
    }
    __syncthreads();
    #pragma unroll
    for (int mt=0;mt<4;mt++)
        #pragma unroll
        for (int nt=0;nt<4;nt++){
            float* cc = acc[mt*4+nt];
            int n = wn + nt*8 + (lane&3)*2;
            #pragma unroll
            for (int hlf=0;hlf<2;hlf++){
                int m = wm + mt*16 + (lane>>2) + hlf*8;
                smE[m*132+n] = cc[hlf*2]; smE[m*132+n+1] = cc[hlf*2+1];
            }
        }
    __syncthreads();
    int row = tid>>1, c0 = (tid&1)*64;
    float* rp = smE + row*132 + c0;
    float mx = -INFINITY;
    for (int j=0;j<64;j++) mx = fmaxf(mx, rp[j]);
    mx = fmaxf(mx, __shfl_xor_sync(0xffffffffu, mx, 1));
    float sum = 0.f;
    for (int j=0;j<64;j++){ float e = expf(rp[j]-mx); rp[j] = e; sum += e; }
    sum += __shfl_xor_sync(0xffffffffu, sum, 1);
    float inv = 1.f/sum;
    if (!var){
        long base = ((long)(b*128+h)*128 + row)*128 + c0;
        for (int j=0;j<64;j+=2)
            ((u32*)Mh)[(base+j)>>1] = pack2(rp[j]*inv, rp[j+1]*inv);
    } else {
        for (int j=0;j<64;j++) rp[j] *= inv;
        __syncthreads();
        if (tid < 128){
            float t = 0.f;
            for (int i=0;i<128;i++) t += smE[i*132+tid];
            mOut[(long)b*HWs + h*128 + tid] = (t>0.1f)?0.f:1.f;
        }
    }
}

// ---- HMMA attend (1-pass) ----
__global__ void __launch_bounds__(256,1) attend_mma(
    const __half* __restrict__ Mh,
    const __half* __restrict__ Vh,
    __half* __restrict__ Oh)
{
    extern __shared__ __align__(16) char smem[];
    u32 sm = smem_u32(smem);
    int tid=threadIdx.x, lane=tid&31, wid=tid>>5;
    int c0 = blockIdx.x*128, bh = blockIdx.y, b = bh>>7, h = bh&127;
    int wm=(wid&1)*64, wn=(wid>>1)*32;
    int lr=lane&15, lc8=(lane>>4)*8;
    int tile=lane>>3, lrow=lane&7;
    float acc[16][4];
    #pragma unroll
    for (int i=0;i<16;i++){ acc[i][0]=0;acc[i][1]=0;acc[i][2]=0;acc[i][3]=0; }
    for (int c=0;c<=4;c++){
        if (c<4){
            u32 st = sm + (u32)(c&1)*20480u;
            int kb = c*32;
            #pragma unroll
            for (int j=0;j<2;j++){
                int o = tid + 256*j, r = o>>2, cb = o&3;
                u32 d = st + (u32)(r*80 + cb*16);
                size_t s = ((size_t)(b*256 + c0 + r))*HWs + h*128 + kb + cb*8;
                cpa(d, Vh+s);
                size_t s2 = (((size_t)(b*128+h)*128 + r))*128 + kb + cb*8;
                cpa(d+10240u, Mh+s2);
            }
            cpcommit();
        }
        if (c==0) continue;
        cpwait((c<4)?1:0);
        __syncthreads();
        u32 sA = sm + (u32)((c-1)&1)*20480u;
        #pragma unroll
        for (int ks=0;ks<32;ks+=16){
            u32 bh_[4][2];
            #pragma unroll
            for (int pr=0;pr<2;pr++){
                u32 off = (u32)(((wn+pr*16+(tile>>1)*8+lrow)*40 + ks + (tile&1)*8)*2);
                u32 r0,r1,r2,r3;
                ldsm4(r0,r1,r2,r3, sA+10240u+off);
                bh_[pr*2][0]=r0; bh_[pr*2][1]=r1; bh_[pr*2+1][0]=r2; bh_[pr*2+1][1]=r3;
            }
            #pragma unroll
            for (int mt=0;mt<4;mt++){
                u32 ah[4];
                u32 off = (u32)((wm+mt*16+lr)*80 + (ks+lc8)*2);
                ldsm4(ah[0],ah[1],ah[2],ah[3], sA+off);
                #pragma unroll
                for (int nt=0;nt<4;nt++)
                    mmah(acc[mt*4+nt], ah, bh_[nt]);
            }
        }
        __syncthreads();
    }
    #pragma unroll
    for (int mt=0;mt<4;mt++)
        #pragma unroll
        for (int nt=0;nt<4;nt++){
            float* cc = acc[mt*4+nt];
            int n = wn + nt*8 + (lane&3)*2;
            #pragma unroll
            for (int hlf=0;hlf<2;hlf++){
                int m = wm + mt*16 + (lane>>2) + hlf*8;
                long idx = ((long)(b*256 + c0 + m))*HWs + h*128 + n;
                ((u32*)Oh)[idx>>1] = pack2(cc[hlf*2], cc[hlf*2+1]);
            }
        }
}

// ---- fused morphology ----
__device__ void morp(float* dst, const float* src, int r, int erode, int D, int t, int NT){
    int r2 = r*r;
    for (int i=t; i<D*D; i+=NT){
        int h = i/D, w = i - h*D;
        float res = erode ? 1.f : 0.f;
        for (int dy=-r; dy<=r; dy++) for (int dx=-r; dx<=r; dx++){
            if (dy*dy+dx*dx > r2) continue;
            int hh=h+dy, ww=w+dx;
            float v = (hh>=0&&hh<D&&ww>=0&&ww<D) ? src[hh*MS+ww] : 0.f;
            if (erode){ if (v<0.5f) res=0.f; } else if (v>0.5f) res=1.f;
        }
        dst[h*MS+w] = res;
    }
}
__global__ void morphall_k(const float* __restrict__ src, float* __restrict__ dst){
    extern __shared__ float sA[];
    float* A = sA; float* B = sA + MS*MS;
    int b = blockIdx.x, t = threadIdx.x, NT = blockDim.x;
    for (int i=t;i<MS*MS;i+=NT){ A[i]=0.f; B[i]=0.f; }
    __syncthreads();
    for (int i=t;i<HWs;i+=NT){ int h=i>>7, w=i&127; A[h*MS+w]=src[(long)b*HWs+i]; }
    __syncthreads();
    morp(B,A,2,1,128,t,NT); __syncthreads();
    morp(A,B,2,0,128,t,NT); __syncthreads();
    morp(B,A,1,0,128,t,NT); __syncthreads();
    morp(A,B,1,1,128,t,NT); __syncthreads();
    for (int i=t;i<MS*MS;i+=NT){
        int h=i/MS, w=i-h*MS;
        float v = 0.f;
        if (h>=3 && h<131 && w>=3 && w<131) v = A[(h-3)*MS + (w-3)];
        B[i] = v;
    }
    __syncthreads();
    morp(A,B,3,0,MS,t,NT); __syncthreads();
    morp(B,A,3,1,MS,t,NT); __syncthreads();
    for (int i=t;i<HWs;i+=NT){ int h=i>>7, w=i&127; dst[(long)b*HWs+i] = 1.f - B[(h+3)*MS + (w+3)]; }
}

extern "C" void kernel_launch(void* const* d_in, const int* in_sizes, int n_in,
                              void* d_out, int out_size) {
    const float* x_p=(const float*)d_in[0];  const float* x_c=(const float*)d_in[1];
    const float* pa_w1=(const float*)d_in[2];const float* pa_b1=(const float*)d_in[3];
    const float* pa_w2=(const float*)d_in[4];const float* pa_b2=(const float*)d_in[5];
    const float* pa_wc=(const float*)d_in[6];const float* pa_bc=(const float*)d_in[7];
    const float* ca_aw1=(const float*)d_in[8];const float* ca_ab1=(const float*)d_in[9];
    const float* ca_aw2=(const float*)d_in[10];const float* ca_ab2=(const float*)d_in[11];
    const float* ca_mw1=(const float*)d_in[12];const float* ca_mb1=(const float*)d_in[13];
    const float* ca_mw2=(const float*)d_in[14];const float* ca_mb2=(const float*)d_in[15];
    const float* b1_w=(const float*)d_in[16];const float* b1_b=(const float*)d_in[17];
    const float* b2_w=(const float*)d_in[18];const float* b2_b=(const float*)d_in[19];
    const float* b3_w=(const float*)d_in[20];const float* b3_b=(const float*)d_in[21];
    const float* fus_w=(const float*)d_in[22];const float* fus_b=(const float*)d_in[23];
    float* out=(float*)d_out;

    float *gate,*amean,*amax,*mA,*vfin,*bcat;
    __half *ih,*il,*wh,*Mh;
    cudaGetSymbolAddress((void**)&gate,g_gate);
    cudaGetSymbolAddress((void**)&amean,g_amean); cudaGetSymbolAddress((void**)&amax,g_amax);
    cudaGetSymbolAddress((void**)&mA,g_mA);
    cudaGetSymbolAddress((void**)&vfin,g_vfinal);
    cudaGetSymbolAddress((void**)&bcat,g_bcat);
    cudaGetSymbolAddress((void**)&ih,g_imgh); cudaGetSymbolAddress((void**)&il,g_imgl);
    cudaGetSymbolAddress((void**)&wh,g_wih);
    cudaGetSymbolAddress((void**)&Mh,g_Mh);
    cudaFuncSetAttribute(gemm_mma, cudaFuncAttributeMaxDynamicSharedMemorySize, GSM);
    cudaFuncSetAttribute(score_mma, cudaFuncAttributeMaxDynamicSharedMemorySize, SSM);
    cudaFuncSetAttribute(attend_mma, cudaFuncAttributeMaxDynamicSharedMemorySize, 40960);
    cudaFuncSetAttribute(morphall_k, cudaFuncAttributeMaxDynamicSharedMemorySize, 2*MS*MS*4);

    const long W1=0, W2=65536, WC=131072, B1=262144, B2=327680, FU=393216;
    const long B2G=524288, B1G=1048576, B3R=1572864;
    dim3 g2(128,16), g1(128,8), g3(128,24);
    dim3 gsc(HH, 16), ga(2, BB*HH);

    pool_k<<<NBCHW/256,256>>>(x_p, ih+IK(3), ih+IK(4), ih+IK(0));
    reduce_k<<<BB*CC,256>>>(x_c, amean, amax, ih+IK(1));
    cagate_k<<<BB,256>>>(amean,amax,ca_aw1,ca_ab1,ca_aw2,ca_ab2,ca_mw1,ca_mb1,ca_mw2,ca_mb2,gate);
    cvtw_k<<<256,256>>>(pa_w1,256,256,0, wh+W1);
    bcat_k<<<5,256>>>(b1_b, b2_b, b3_b, bcat);
    // merged h1+h2 (relu) -> I5,I6
    gemm_mma<<<g2,256,GSM>>>(wh+W1,0,0,256, ih+IK(3),0,IK(1), 0,ih+IK(5),0,IK(1),
                             pa_b1,0,1, 0,0,0);
    cvtw_k<<<256,256>>>(pa_w2,256,256,0, wh+W2);
    gemm_mma<<<g2,256,GSM>>>(wh+W2,0,0,256, ih+IK(5),0,IK(1), 0,ih+IK(7),0,IK(1),
                             pa_b2,0,2, ih+IK(3),IK(1),0);
    cvtw_k<<<512,256>>>(pa_wc,512,512,0, wh+WC);
    gemm_mma<<<g1,256,GSM>>>(wh+WC,0,0,512, ih+IK(7),ih+IK(8),0, 0,ih+IK(2),0,0,
                             pa_bc,0,3, x_p,0,0);
    cvtw_k<<<256,256>>>(b1_w,256,256,0, wh+B1);
    cvtw_k<<<256,256>>>(b2_w,256,256,0, wh+B2);
    // merged Q1+S2 -> I3,I4 (hi; lo for Q1)
    gemm_mma<<<g2,256,GSM>>>(wh+B1,0,65536,256, ih+IK(2),0,0, 0,ih+IK(3),il+IK(3),IK(1),
                             bcat,256,0, 0,0,0);
    cvtw_k<<<2048,256>>>(b2_w,256,256,gate, wh+B2G);
    cvtw_k<<<2048,256>>>(b1_w,256,256,gate, wh+B1G);
    cvtw_k<<<2048,256>>>(b3_w,256,256,0, wh+B3R);
    // merged S1+Q2+v3 (per-batch stride) -> I5,I6,I7 (hi only)
    gemm_mma<<<g3,256,GSM>>>(wh+B2G,65536,524288,256, ih+IK(1),0,0, 0,ih+IK(5),0,IK(1),
                             bcat+512,256,0, 0,0,0);
    // merged scores: var0 = (Q1=I3+lo, S1=I5) -> M; var1 = (Q2=I6, S2=I4) -> mask
    score_mma<<<gsc,256,SSM>>>(ih+IK(3),il+IK(3), ih+IK(5), ih+IK(6), ih+IK(4), Mh, mA);
    // morphology
    morphall_k<<<BB,1024,2*MS*MS*4>>>(mA, vfin);
    // attend -> I8
    attend_mma<<<ga,256,40960>>>(Mh, ih+IK(7), ih+IK(8));
    // fusion
    cvtw_k<<<512,256>>>(fus_w,513,512,0, wh+FU);
    gemm_mma<<<g1,256,GSM>>>(wh+FU,0,0,512, ih+IK(8),ih+IK(0),0, out,0,0,0,
                             fus_b,0,4, vfin,0,fus_w);
}